// round 13
// baseline (speedup 1.0000x reference)
#include <cuda_runtime.h>
#include <cstdint>

#define M_GT  512
#define N_CTX 1024
#define FEAT  1024
#define NG    16
#define DK    64
#define MN    (M_GT * N_CTX)   // 524288

// ---------------- device scratch (static globals; no allocation) ------------
__device__ float g_Q [M_GT * FEAT];
__device__ float g_K [N_CTX * FEAT];
__device__ float g_Ut[FEAT * M_GT];    // Ut[o][m]
__device__ float g_Vt[FEAT * N_CTX];   // Vt[o][n]
__device__ float g_S [NG * MN];        // scores  (G, M, N)
__device__ float g_St[NG * MN];        // scores^T (G, N, M)
__device__ float g_L1[NG * MN];        // weights gt  (G, M, N)
__device__ float g_L2[NG * MN];        // weights ctx (G, N, M)
__device__ float g_tabA[M_GT * 36];    // per-box sin/cos tables (gt boxes)
__device__ float g_tabB[N_CTX * 36];   // per-box sin/cos tables (ctx boxes)

// 1000^(-j/8)
__constant__ float c_invdim[8] = {
    1.0f, 0.4216965034f, 0.1778279410f, 0.0749894209f,
    0.0316227766f, 0.0133352143f, 0.0056234133f, 0.0023713737f
};

// ======================= helpers ==========================
__device__ __forceinline__ uint32_t f2tf(float x) {
    uint32_t r;
    asm("cvt.rna.tf32.f32 %0, %1;" : "=r"(r) : "f"(x));
    return r;
}

__device__ __forceinline__ void mma8(float* c, const uint32_t* a, const uint32_t* b) {
    asm volatile(
        "mma.sync.aligned.m16n8k8.row.col.f32.tf32.tf32.f32 "
        "{%0,%1,%2,%3}, {%4,%5,%6,%7}, {%8,%9}, {%0,%1,%2,%3};"
        : "+f"(c[0]), "+f"(c[1]), "+f"(c[2]), "+f"(c[3])
        : "r"(a[0]), "r"(a[1]), "r"(a[2]), "r"(a[3]), "r"(b[0]), "r"(b[1]));
}

__device__ __forceinline__ void cp16(uint32_t s, const void* g) {
    asm volatile("cp.async.cg.shared.global [%0], [%1], 16;" :: "r"(s), "l"(g));
}
#define CP_COMMIT() asm volatile("cp.async.commit_group;" ::: "memory")
#define CP_WAIT1()  asm volatile("cp.async.wait_group 1;" ::: "memory")
#define CP_WAIT0()  asm volatile("cp.async.wait_group 0;" ::: "memory")

#define LDP 36   // smem row pitch (floats)

template <int ROWS>
__device__ __forceinline__ void issue_chunk(const float* __restrict__ g, int ld,
                                            uint32_t smbase, int tid)
{
#pragma unroll
    for (int i = 0; i < ROWS / 32; i++) {
        int idx = tid + i * 256;
        int r = idx >> 3, c = (idx & 7) << 2;
        cp16(smbase + (uint32_t)(r * LDP + c) * 4u, g + (size_t)r * ld + c);
    }
}

template <int ROWS>
__device__ __forceinline__ void stage(const float* __restrict__ g, int ld,
                                      uint32_t* __restrict__ sm, int tid)
{
#pragma unroll
    for (int i = 0; i < ROWS / 32; i++) {
        int idx = tid + i * 256;
        int r = idx >> 3, c = (idx & 7) << 2;
        float4 v = *(const float4*)(g + (size_t)r * ld + c);
        uint4 t;
        t.x = f2tf(v.x); t.y = f2tf(v.y); t.z = f2tf(v.z); t.w = f2tf(v.w);
        *(uint4*)(sm + r * LDP + c) = t;
    }
}

// ---------------------------------------------------------------------------
// boxtab_k: per-box sin/cos tables for the separable dw/dh embedding dims.
// ---------------------------------------------------------------------------
__global__ void boxtab_k(const float4* __restrict__ box,
                         const float4* __restrict__ ctx_box)
{
    int i = blockIdx.x * 128 + threadIdx.x;
    float4 Bx; float* dst;
    if (i < M_GT) { Bx = box[i]; dst = g_tabA + (size_t)i * 36; }
    else if (i < M_GT + N_CTX) { Bx = ctx_box[i - M_GT]; dst = g_tabB + (size_t)(i - M_GT) * 36; }
    else return;
    float lw = 100.0f * __logf(Bx.z - Bx.x + 1.0f);
    float lh = 100.0f * __logf(Bx.w - Bx.y + 1.0f);
#pragma unroll
    for (int j = 0; j < 8; j++) {
        float s, c;
        __sincosf(lw * c_invdim[j], &s, &c);
        dst[2 * j] = s; dst[2 * j + 1] = c;
        __sincosf(lh * c_invdim[j], &s, &c);
        dst[16 + 2 * j] = s; dst[17 + 2 * j] = c;
    }
}

// ---------------------------------------------------------------------------
// proj_mma: C = A @ W^T (+bias along N). 128x128 tiles, K=1024.
// ---------------------------------------------------------------------------
#define PROJ_BUF (128 * LDP * 2)

__global__ __launch_bounds__(256, 2) void proj_mma(
    const float* __restrict__ feat, const float* __restrict__ ctx_feat,
    const float* __restrict__ w_gt, const float* __restrict__ b_gt,
    const float* __restrict__ w_ctx, const float* __restrict__ b_ctx,
    const float* __restrict__ w_conv)
{
    const float* A; const float* W; const float* bias; float* C;
    int Mrows, Ncols;
    switch (blockIdx.z) {
    case 0:  A = feat;   W = w_gt;     bias = b_gt;  C = g_Q;  Mrows = M_GT;  Ncols = FEAT;  break;
    case 1:  A = ctx_feat; W = w_ctx;  bias = b_ctx; C = g_K;  Mrows = N_CTX; Ncols = FEAT;  break;
    case 2:  A = w_conv; W = feat;     bias = 0;     C = g_Ut; Mrows = FEAT;  Ncols = M_GT;  break;
    default: A = w_conv; W = ctx_feat; bias = 0;     C = g_Vt; Mrows = FEAT;  Ncols = N_CTX; break;
    }
    int bm = blockIdx.y * 128, bn = blockIdx.x * 128;
    if (bm >= Mrows || bn >= Ncols) return;

    extern __shared__ float dsm[];
    uint32_t smb = (uint32_t)__cvta_generic_to_shared(dsm);

    int tid = threadIdx.x, wid = tid >> 5, lane = tid & 31;
    int g4 = lane >> 2, tig = lane & 3;
    int wm = (wid & 1) * 64, wn = (wid >> 1) * 32;

    float acc[4][4][4];
#pragma unroll
    for (int i = 0; i < 4; i++)
#pragma unroll
        for (int j = 0; j < 4; j++)
#pragma unroll
            for (int q = 0; q < 4; q++) acc[i][j][q] = 0.0f;

    const float* Ab = A + (size_t)bm * FEAT;
    const float* Wb = W + (size_t)bn * FEAT;

    issue_chunk<128>(Ab, FEAT, smb, tid);
    issue_chunk<128>(Wb, FEAT, smb + 128 * LDP * 4u, tid);
    CP_COMMIT();

    const int NCH = FEAT / 32;
    for (int ch = 0; ch < NCH; ch++) {
        int buf = ch & 1;
        if (ch + 1 < NCH) {
            uint32_t nb = smb + (uint32_t)((ch + 1) & 1) * PROJ_BUF * 4u;
            issue_chunk<128>(Ab + (ch + 1) * 32, FEAT, nb, tid);
            issue_chunk<128>(Wb + (ch + 1) * 32, FEAT, nb + 128 * LDP * 4u, tid);
            CP_COMMIT();
            CP_WAIT1();
        } else {
            CP_WAIT0();
        }
        __syncthreads();
        const float* As = dsm + buf * PROJ_BUF;
        const float* Bs = As + 128 * LDP;
#pragma unroll
        for (int kk = 0; kk < 4; kk++) {
            int k0 = kk * 8 + tig;
            uint32_t bf[4][2];
#pragma unroll
            for (int j = 0; j < 4; j++) {
                int rn = (wn + j * 8 + g4) * LDP;
                bf[j][0] = f2tf(Bs[rn + k0]);
                bf[j][1] = f2tf(Bs[rn + k0 + 4]);
            }
#pragma unroll
            for (int i = 0; i < 4; i++) {
                int r0 = (wm + i * 16 + g4) * LDP;
                uint32_t af[4];
                af[0] = f2tf(As[r0 + k0]);
                af[1] = f2tf(As[r0 + 8 * LDP + k0]);
                af[2] = f2tf(As[r0 + k0 + 4]);
                af[3] = f2tf(As[r0 + 8 * LDP + k0 + 4]);
#pragma unroll
                for (int j = 0; j < 4; j++) mma8(acc[i][j], af, bf[j]);
            }
        }
        __syncthreads();
    }

#pragma unroll
    for (int i = 0; i < 4; i++) {
        int row = bm + wm + i * 16 + g4;
#pragma unroll
        for (int j = 0; j < 4; j++) {
            int col = bn + wn + j * 8 + 2 * tig;
            float b0 = bias ? bias[col] : 0.0f;
            float b1 = bias ? bias[col + 1] : 0.0f;
            float2 o0, o1;
            o0.x = acc[i][j][0] + b0; o0.y = acc[i][j][1] + b1;
            o1.x = acc[i][j][2] + b0; o1.y = acc[i][j][3] + b1;
            *(float2*)(C + (size_t)row * Ncols + col)       = o0;
            *(float2*)(C + (size_t)(row + 8) * Ncols + col) = o1;
        }
    }
}

// ---------------------------------------------------------------------------
// scores_mma: S[g,m,n] = 0.125 * Q.K ; St[g,n,m] via smem transpose.
// ---------------------------------------------------------------------------
#define TP 68

__global__ __launch_bounds__(256, 2) void scores_mma()
{
    int g = blockIdx.z;
    int bm = blockIdx.y * 128, bn = blockIdx.x * 128;
    const float* A = g_Q + (size_t)bm * FEAT + g * DK;
    const float* B = g_K + (size_t)bn * FEAT + g * DK;
    float* C  = g_S  + (size_t)g * MN;
    float* Ct = g_St + (size_t)g * MN;

    __shared__ __align__(16) uint32_t sbuf[2 * 128 * LDP];
    uint32_t* As = sbuf;
    uint32_t* Bs = sbuf + 128 * LDP;
    float* T = (float*)sbuf;

    int tid = threadIdx.x, wid = tid >> 5, lane = tid & 31;
    int g4 = lane >> 2, tig = lane & 3;
    int wm = (wid & 1) * 64, wn = (wid >> 1) * 32;

    float acc[4][4][4];
#pragma unroll
    for (int i = 0; i < 4; i++)
#pragma unroll
        for (int j = 0; j < 4; j++)
#pragma unroll
            for (int q = 0; q < 4; q++) acc[i][j][q] = 0.0f;

    for (int ch = 0; ch < 2; ch++) {
        stage<128>(A + ch * 32, FEAT, As, tid);
        stage<128>(B + ch * 32, FEAT, Bs, tid);
        __syncthreads();
#pragma unroll
        for (int kk = 0; kk < 4; kk++) {
            int k0 = kk * 8 + tig;
            uint32_t bf[4][2];
#pragma unroll
            for (int j = 0; j < 4; j++) {
                int rn = (wn + j * 8 + g4) * LDP;
                bf[j][0] = Bs[rn + k0];
                bf[j][1] = Bs[rn + k0 + 4];
            }
#pragma unroll
            for (int i = 0; i < 4; i++) {
                int r0 = (wm + i * 16 + g4) * LDP;
                uint32_t af[4];
                af[0] = As[r0 + k0];
                af[1] = As[r0 + 8 * LDP + k0];
                af[2] = As[r0 + k0 + 4];
                af[3] = As[r0 + 8 * LDP + k0 + 4];
#pragma unroll
                for (int j = 0; j < 4; j++) mma8(acc[i][j], af, bf[j]);
            }
        }
        __syncthreads();
    }

#pragma unroll
    for (int i = 0; i < 4; i++) {
        int row = bm + wm + i * 16 + g4;
#pragma unroll
        for (int j = 0; j < 4; j++) {
            int col = bn + wn + j * 8 + 2 * tig;
            float2 o0, o1;
            o0.x = acc[i][j][0] * 0.125f; o0.y = acc[i][j][1] * 0.125f;
            o1.x = acc[i][j][2] * 0.125f; o1.y = acc[i][j][3] * 0.125f;
            *(float2*)(C + (size_t)row * N_CTX + col)       = o0;
            *(float2*)(C + (size_t)(row + 8) * N_CTX + col) = o1;
        }
    }

    for (int hh = 0; hh < 2; hh++) {
        __syncthreads();
        if ((wid & 1) == hh) {
#pragma unroll
            for (int i = 0; i < 4; i++) {
                int rl = i * 16 + g4;
#pragma unroll
                for (int j = 0; j < 4; j++) {
                    int col = wn + j * 8 + 2 * tig;
                    T[col * TP + rl]            = acc[i][j][0] * 0.125f;
                    T[(col + 1) * TP + rl]      = acc[i][j][1] * 0.125f;
                    T[col * TP + rl + 8]        = acc[i][j][2] * 0.125f;
                    T[(col + 1) * TP + rl + 8]  = acc[i][j][3] * 0.125f;
                }
            }
        }
        __syncthreads();
        int col = tid >> 1, seg = (tid & 1) << 5;
        const float* src = T + col * TP + seg;
        float* dst = Ct + (size_t)(bn + col) * M_GT + bm + hh * 64 + seg;
#pragma unroll
        for (int k = 0; k < 8; k++)
            *(float4*)(dst + k * 4) = *(const float4*)(src + k * 4);
    }
}

// ---------------------------------------------------------------------------
// attn_mma: z 0..15 gt, z 16..31 ctx. 128x64 tiles, warp tile 64x16.
// ---------------------------------------------------------------------------
#define ATTN_BUF (128 * LDP + 64 * LDP)

__global__ __launch_bounds__(256, 2) void attn_mma(
    const float* __restrict__ b_conv, float* __restrict__ out_gt,
    float* __restrict__ out_ctx)
{
    int z = blockIdx.z;
    int g = z & 15;
    bool gt = z < 16;
    const float* A = gt ? g_L1 + (size_t)g * MN : g_L2 + (size_t)g * MN;
    const float* B = gt ? g_Vt + (size_t)(g * DK) * N_CTX
                        : g_Ut + (size_t)(g * DK) * M_GT;
    float* C  = gt ? out_gt : out_ctx;
    int Mrows = gt ? M_GT : N_CTX;
    int Ktot  = gt ? N_CTX : M_GT;
    int bm = blockIdx.y * 128;
    if (bm >= Mrows) return;

    extern __shared__ float dsm[];
    uint32_t smb = (uint32_t)__cvta_generic_to_shared(dsm);

    int tid = threadIdx.x, wid = tid >> 5, lane = tid & 31;
    int g4 = lane >> 2, tig = lane & 3;
    int wm = (wid & 1) * 64, wn = (wid >> 1) * 16;

    float acc[4][2][4];
#pragma unroll
    for (int i = 0; i < 4; i++)
#pragma unroll
        for (int j = 0; j < 2; j++)
#pragma unroll
            for (int q = 0; q < 4; q++) acc[i][j][q] = 0.0f;

    const float* Ab = A + (size_t)bm * Ktot;

    issue_chunk<128>(Ab, Ktot, smb, tid);
    issue_chunk<64>(B, Ktot, smb + 128 * LDP * 4u, tid);
    CP_COMMIT();

    int NCH = Ktot / 32;
    for (int ch = 0; ch < NCH; ch++) {
        int buf = ch & 1;
        if (ch + 1 < NCH) {
            uint32_t nb = smb + (uint32_t)((ch + 1) & 1) * ATTN_BUF * 4u;
            issue_chunk<128>(Ab + (ch + 1) * 32, Ktot, nb, tid);
            issue_chunk<64>(B + (ch + 1) * 32, Ktot, nb + 128 * LDP * 4u, tid);
            CP_COMMIT();
            CP_WAIT1();
        } else {
            CP_WAIT0();
        }
        __syncthreads();
        const float* As = dsm + buf * ATTN_BUF;
        const float* Bs = As + 128 * LDP;
#pragma unroll
        for (int kk = 0; kk < 4; kk++) {
            int k0 = kk * 8 + tig;
            uint32_t bf[2][2];
#pragma unroll
            for (int j = 0; j < 2; j++) {
                int rn = (wn + j * 8 + g4) * LDP;
                bf[j][0] = f2tf(Bs[rn + k0]);
                bf[j][1] = f2tf(Bs[rn + k0 + 4]);
            }
#pragma unroll
            for (int i = 0; i < 4; i++) {
                int r0 = (wm + i * 16 + g4) * LDP;
                uint32_t af[4];
                af[0] = f2tf(As[r0 + k0]);
                af[1] = f2tf(As[r0 + 8 * LDP + k0]);
                af[2] = f2tf(As[r0 + k0 + 4]);
                af[3] = f2tf(As[r0 + 8 * LDP + k0 + 4]);
#pragma unroll
                for (int j = 0; j < 2; j++) mma8(acc[i][j], af, bf[j]);
            }
        }
        __syncthreads();
    }

#pragma unroll
    for (int i = 0; i < 4; i++) {
        int row = bm + wm + i * 16 + g4;
#pragma unroll
        for (int j = 0; j < 2; j++) {
            int col = g * DK + wn + j * 8 + 2 * tig;
            float b0 = b_conv[col], b1 = b_conv[col + 1];
            float2 o0, o1;
            o0.x = acc[i][j][0] + b0; o0.y = acc[i][j][1] + b1;
            o1.x = acc[i][j][2] + b0; o1.y = acc[i][j][3] + b1;
            *(float2*)(C + (size_t)row * FEAT + col)       = o0;
            *(float2*)(C + (size_t)(row + 8) * FEAT + col) = o1;
        }
    }
}

// ---------------------------------------------------------------------------
// pos_soft<NCOLS>: fused pos-embedding + logit + row softmax, tensor-core
// pos-linear. A-side 2-term hi/lo + W-side 2-term hi/lo (3 mma terms:
// ah*bh + ah*bl + al*bh) — the al term is REQUIRED: log() amplifies absolute
// pos error near the 1e-6 clamp (R12 failure). Scores added in phase 2 via
// coalesced float4 loads.
// ---------------------------------------------------------------------------
template <int NCOLS>
__global__ __launch_bounds__(NCOLS / 4, 768 / (NCOLS / 4)) void pos_soft(
    const float4* __restrict__ boxA, const float4* __restrict__ boxB,
    const float* __restrict__ tabA, const float* __restrict__ tabB,
    const float* __restrict__ w_pos, const float* __restrict__ b_pos,
    const float* __restrict__ Sb, float* __restrict__ L)
{
    constexpr int NT = NCOLS / 4;
    constexpr int NW = NT / 32;
    constexpr int SLP = NCOLS + 4;            // smem logits pitch
    extern __shared__ float sl[];             // [NG][SLP]
    __shared__ float wbh[16 * 68];            // w_pos tf32-hi, pitch 68
    __shared__ float wbl[16 * 68];            // w_pos tf32-lo
    __shared__ float bp[NG];
    __shared__ float rbuf[NG * (NW + 1)];

    int tid = threadIdx.x, wid = tid >> 5, lane = tid & 31;
    int g4 = lane >> 2, tig = lane & 3;

    for (int i = tid; i < 1024; i += NT) {
        int g = i >> 6, f = i & 63;
        float w = w_pos[i];
        uint32_t hb = f2tf(w);
        float hf = __uint_as_float(hb);
        wbh[g * 68 + f] = hf;
        wbl[g * 68 + f] = __uint_as_float(f2tf(w - hf));
    }
    if (tid < NG) bp[tid] = b_pos[tid];
    __syncthreads();

    int r = blockIdx.x;
    float4 A = boxA[r];
    float bw = A.z - A.x + 1.0f, bh = A.w - A.y + 1.0f;
    float cx = 0.5f * (A.x + A.z), cy = 0.5f * (A.y + A.w);
    float rbw = 1.0f / bw, rbh = 1.0f / bh;
    float ivA = c_invdim[tig], ivB = c_invdim[tig + 4];

    const float* tr = tabA + (size_t)r * 36;
    float2 rw0 = *(const float2*)(tr + 2 * tig);
    float2 rw1 = *(const float2*)(tr + 2 * tig + 8);
    float2 rh0 = *(const float2*)(tr + 16 + 2 * tig);
    float2 rh1 = *(const float2*)(tr + 24 + 2 * tig);

    for (int mt = 0; mt < 8; mt++) {
        int base = wid * 128 + mt * 16;
        float a[2][8][2];   // [col ci][kk][k-half]
#pragma unroll
        for (int ci = 0; ci < 2; ci++) {
            int col = base + ci * 8 + g4;
            float4 Bx = boxB[col];
            float p0 = 100.0f * __logf(fmaxf(fabsf((cx - 0.5f * (Bx.x + Bx.z)) * rbw), 1e-3f));
            float p1 = 100.0f * __logf(fmaxf(fabsf((cy - 0.5f * (Bx.y + Bx.w)) * rbh), 1e-3f));
            float s, c;
            __sincosf(p0 * ivA, &s, &c);
            a[ci][0][0] = fmaxf(s, 0.0f); a[ci][1][0] = fmaxf(c, 0.0f);
            __sincosf(p0 * ivB, &s, &c);
            a[ci][0][1] = fmaxf(s, 0.0f); a[ci][1][1] = fmaxf(c, 0.0f);
            __sincosf(p1 * ivA, &s, &c);
            a[ci][2][0] = fmaxf(s, 0.0f); a[ci][3][0] = fmaxf(c, 0.0f);
            __sincosf(p1 * ivB, &s, &c);
            a[ci][2][1] = fmaxf(s, 0.0f); a[ci][3][1] = fmaxf(c, 0.0f);
            const float* tc = tabB + (size_t)col * 36;
            float2 cw0 = *(const float2*)(tc + 2 * tig);
            float2 cw1 = *(const float2*)(tc + 2 * tig + 8);
            float2 ch0 = *(const float2*)(tc + 16 + 2 * tig);
            float2 ch1 = *(const float2*)(tc + 24 + 2 * tig);
            a[ci][4][0] = fmaxf(cw0.x * rw0.y - cw0.y * rw0.x, 0.0f);
            a[ci][4][1] = fmaxf(cw1.x * rw1.y - cw1.y * rw1.x, 0.0f);
            a[ci][5][0] = fmaxf(cw0.y * rw0.y + cw0.x * rw0.x, 0.0f);
            a[ci][5][1] = fmaxf(cw1.y * rw1.y + cw1.x * rw1.x, 0.0f);
            a[ci][6][0] = fmaxf(ch0.x * rh0.y - ch0.y * rh0.x, 0.0f);
            a[ci][6][1] = fmaxf(ch1.x * rh1.y - ch1.y * rh1.x, 0.0f);
            a[ci][7][0] = fmaxf(ch0.y * rh0.y + ch0.x * rh0.x, 0.0f);
            a[ci][7][1] = fmaxf(ch1.y * rh1.y + ch1.x * rh1.x, 0.0f);
        }

        float acc[2][4];
#pragma unroll
        for (int j = 0; j < 2; j++)
#pragma unroll
            for (int q = 0; q < 4; q++) acc[j][q] = 0.0f;

#pragma unroll
        for (int kk = 0; kk < 8; kk++) {
            uint32_t ah[4], al[4];
#pragma unroll
            for (int q = 0; q < 4; q++) {
                float v = a[q & 1][kk][q >> 1];
                uint32_t h = f2tf(v);
                ah[q] = h;
                al[q] = f2tf(v - __uint_as_float(h));
            }
            int ko = 8 * kk + tig;
#pragma unroll
            for (int j = 0; j < 2; j++) {
                int rb = (8 * j + g4) * 68 + ko;
                uint32_t bh2[2], bl2[2];
                bh2[0] = __float_as_uint(wbh[rb]);
                bh2[1] = __float_as_uint(wbh[rb + 4]);
                bl2[0] = __float_as_uint(wbl[rb]);
                bl2[1] = __float_as_uint(wbl[rb + 4]);
                mma8(acc[j], ah, bh2);
                mma8(acc[j], ah, bl2);
                mma8(acc[j], al, bh2);
            }
        }

        int cA = base + g4, cB = cA + 8;
#pragma unroll
        for (int j = 0; j < 2; j++) {
            int ga = 8 * j + 2 * tig, gb = ga + 1;
            sl[ga * SLP + cA] = __logf(fmaxf(acc[j][0] + bp[ga], 1e-6f));
            sl[gb * SLP + cA] = __logf(fmaxf(acc[j][1] + bp[gb], 1e-6f));
            sl[ga * SLP + cB] = __logf(fmaxf(acc[j][2] + bp[ga], 1e-6f));
            sl[gb * SLP + cB] = __logf(fmaxf(acc[j][3] + bp[gb], 1e-6f));
        }
    }
    __syncthreads();

    // ---- phase 2: add scores (coalesced) + row softmax ----
    int c0 = tid * 4;
    size_t sro = (size_t)r * NCOLS + c0;
    float mx[NG];
#pragma unroll
    for (int g = 0; g < NG; g++) {
        float4 v = *(float4*)&sl[g * SLP + c0];
        float4 sc = *(const float4*)(Sb + (size_t)g * MN + sro);
        v.x += sc.x; v.y += sc.y; v.z += sc.z; v.w += sc.w;
        *(float4*)&sl[g * SLP + c0] = v;
        mx[g] = fmaxf(fmaxf(v.x, v.y), fmaxf(v.z, v.w));
    }
#pragma unroll
    for (int g = 0; g < NG; g++) {
#pragma unroll
        for (int o = 16; o; o >>= 1)
            mx[g] = fmaxf(mx[g], __shfl_xor_sync(0xffffffffu, mx[g], o));
    }
    if (lane == 0) {
#pragma unroll
        for (int g = 0; g < NG; g++) rbuf[g * (NW + 1) + wid] = mx[g];
    }
    __syncthreads();
    if (tid < NG) {
        float t = rbuf[tid * (NW + 1)];
#pragma unroll
        for (int w = 1; w < NW; w++) t = fmaxf(t, rbuf[tid * (NW + 1) + w]);
        rbuf[tid * (NW + 1) + NW] = t;
    }
    __syncthreads();

    float sum[NG];
#pragma unroll
    for (int g = 0; g < NG; g++) {
        float m = rbuf[g * (NW + 1) + NW];
        float4 v = *(float4*)&sl[g * SLP + c0];
        v.x = __expf(v.x - m); v.y = __expf(v.y - m);
        v.z = __expf(v.z - m); v.w = __expf(v.w - m);
        *(float4*)&sl[g * SLP + c0] = v;
        sum[g] = (v.x + v.y) + (v.z + v.w);
    }
    __syncthreads();
#pragma unroll
    for (int g = 0; g < NG; g++) {
#pragma unroll
        for (int o = 16; o; o >>= 1)
            sum[g] += __shfl_xor_sync(0xffffffffu, sum[g], o);
    }
    if (lane == 0) {
#pragma unroll
        for (int g = 0; g < NG; g++) rbuf[g * (NW + 1) + wid] = sum[g];
    }
    __syncthreads();
    if (tid < NG) {
        float t = 0.0f;
#pragma unroll
        for (int w = 0; w < NW; w++) t += rbuf[tid * (NW + 1) + w];
        rbuf[tid * (NW + 1) + NW] = t;
    }
    __syncthreads();

#pragma unroll
    for (int g = 0; g < NG; g++) {
        float inv = __frcp_rn(rbuf[g * (NW + 1) + NW]);
        float4 v = *(float4*)&sl[g * SLP + c0];
        v.x *= inv; v.y *= inv; v.z *= inv; v.w *= inv;
        *(float4*)(L + (size_t)g * MN + (size_t)r * NCOLS + c0) = v;
    }
}

// ---------------------------------------------------------------------------
extern "C" void kernel_launch(void* const* d_in, const int* in_sizes, int n_in,
                              void* d_out, int out_size)
{
    (void)in_sizes; (void)n_in; (void)out_size;
    const float* feat      = (const float*)d_in[0];
    const float* ctx_feat  = (const float*)d_in[1];
    const float* box       = (const float*)d_in[2];
    const float* ctx_box   = (const float*)d_in[3];
    const float* w_fc_gt   = (const float*)d_in[4];
    const float* b_fc_gt   = (const float*)d_in[5];
    const float* w_fc_ctx  = (const float*)d_in[6];
    const float* b_fc_ctx  = (const float*)d_in[7];
    const float* w_pos_gt  = (const float*)d_in[8];
    const float* b_pos_gt  = (const float*)d_in[9];
    const float* w_pos_ctx = (const float*)d_in[10];
    const float* b_pos_ctx = (const float*)d_in[11];
    const float* w_conv    = (const float*)d_in[12];
    const float* b_conv    = (const float*)d_in[13];

    float* out = (float*)d_out;
    float* out_gt  = out;
    float* out_ctx = out + (size_t)M_GT * FEAT;

    float *S, *St, *L1, *L2, *tabA, *tabB;
    cudaGetSymbolAddress((void**)&S,    g_S);
    cudaGetSymbolAddress((void**)&St,   g_St);
    cudaGetSymbolAddress((void**)&L1,   g_L1);
    cudaGetSymbolAddress((void**)&L2,   g_L2);
    cudaGetSymbolAddress((void**)&tabA, g_tabA);
    cudaGetSymbolAddress((void**)&tabB, g_tabB);

    static int attr_done = 0;
    if (!attr_done) {
        cudaFuncSetAttribute(proj_mma, cudaFuncAttributeMaxDynamicSharedMemorySize,
                             2 * PROJ_BUF * 4);
        cudaFuncSetAttribute(attn_mma, cudaFuncAttributeMaxDynamicSharedMemorySize,
                             2 * ATTN_BUF * 4);
        cudaFuncSetAttribute(pos_soft<N_CTX>, cudaFuncAttributeMaxDynamicSharedMemorySize,
                             NG * (N_CTX + 4) * 4);
        cudaFuncSetAttribute(pos_soft<M_GT>, cudaFuncAttributeMaxDynamicSharedMemorySize,
                             NG * (M_GT + 4) * 4);
        attr_done = 1;
    }

    // 0) per-box sin/cos tables
    boxtab_k<<<(M_GT + N_CTX + 127) / 128, 128>>>((const float4*)box,
                                                  (const float4*)ctx_box);
    // 1) Q, K, Ut, Vt projections
    proj_mma<<<dim3(8, 8, 4), 256, 2 * PROJ_BUF * 4>>>(
        feat, ctx_feat, w_fc_gt, b_fc_gt, w_fc_ctx, b_fc_ctx, w_conv);
    // 2) scores S + St
    scores_mma<<<dim3(8, 4, 16), 256>>>();
    // 3) fused pos-embedding + logits + softmax
    pos_soft<N_CTX><<<M_GT, N_CTX / 4, NG * (N_CTX + 4) * 4>>>(
        (const float4*)box, (const float4*)ctx_box, tabA, tabB,
        w_pos_gt, b_pos_gt, S, L1);
    pos_soft<M_GT><<<N_CTX, M_GT / 4, NG * (M_GT + 4) * 4>>>(
        (const float4*)ctx_box, (const float4*)box, tabB, tabA,
        w_pos_ctx, b_pos_ctx, St, L2);
    // 4) attention output
    attn_mma<<<dim3(1, 8, 32), 256, 2 * ATTN_BUF * 4>>>(b_conv, out_gt, out_ctx);
}

// round 14
// speedup vs baseline: 1.0418x; 1.0418x over previous
#include <cuda_runtime.h>
#include <cstdint>

#define M_GT  512
#define N_CTX 1024
#define FEAT  1024
#define NG    16
#define DK    64
#define MN    (M_GT * N_CTX)   // 524288

// ---------------- device scratch (static globals; no allocation) ------------
__device__ float g_Q [M_GT * FEAT];
__device__ float g_K [N_CTX * FEAT];
__device__ float g_Ut[FEAT * M_GT];    // Ut[o][m]
__device__ float g_Vt[FEAT * N_CTX];   // Vt[o][n]
__device__ float g_E [NG * MN];        // exp(scores)  (G, M, N)
__device__ float g_Et[NG * MN];        // exp(scores)^T (G, N, M)
__device__ float g_L1[NG * MN];        // weights gt  (G, M, N)
__device__ float g_L2[NG * MN];        // weights ctx (G, N, M)
__device__ float g_tabA[M_GT * 36];    // per-box sin/cos tables (gt boxes)
__device__ float g_tabB[N_CTX * 36];   // per-box sin/cos tables (ctx boxes)

// 1000^(-j/8)
__constant__ float c_invdim[8] = {
    1.0f, 0.4216965034f, 0.1778279410f, 0.0749894209f,
    0.0316227766f, 0.0133352143f, 0.0056234133f, 0.0023713737f
};

// ======================= helpers ==========================
__device__ __forceinline__ uint32_t f2tf(float x) {
    uint32_t r;
    asm("cvt.rna.tf32.f32 %0, %1;" : "=r"(r) : "f"(x));
    return r;
}

__device__ __forceinline__ void mma8(float* c, const uint32_t* a, const uint32_t* b) {
    asm volatile(
        "mma.sync.aligned.m16n8k8.row.col.f32.tf32.tf32.f32 "
        "{%0,%1,%2,%3}, {%4,%5,%6,%7}, {%8,%9}, {%0,%1,%2,%3};"
        : "+f"(c[0]), "+f"(c[1]), "+f"(c[2]), "+f"(c[3])
        : "r"(a[0]), "r"(a[1]), "r"(a[2]), "r"(a[3]), "r"(b[0]), "r"(b[1]));
}

__device__ __forceinline__ void cp16(uint32_t s, const void* g) {
    asm volatile("cp.async.cg.shared.global [%0], [%1], 16;" :: "r"(s), "l"(g));
}
#define CP_COMMIT() asm volatile("cp.async.commit_group;" ::: "memory")
#define CP_WAIT1()  asm volatile("cp.async.wait_group 1;" ::: "memory")
#define CP_WAIT0()  asm volatile("cp.async.wait_group 0;" ::: "memory")

#define LDP 36   // smem row pitch (floats)

template <int ROWS>
__device__ __forceinline__ void issue_chunk(const float* __restrict__ g, int ld,
                                            uint32_t smbase, int tid)
{
#pragma unroll
    for (int i = 0; i < ROWS / 32; i++) {
        int idx = tid + i * 256;
        int r = idx >> 3, c = (idx & 7) << 2;
        cp16(smbase + (uint32_t)(r * LDP + c) * 4u, g + (size_t)r * ld + c);
    }
}

template <int ROWS>
__device__ __forceinline__ void stage(const float* __restrict__ g, int ld,
                                      uint32_t* __restrict__ sm, int tid)
{
#pragma unroll
    for (int i = 0; i < ROWS / 32; i++) {
        int idx = tid + i * 256;
        int r = idx >> 3, c = (idx & 7) << 2;
        float4 v = *(const float4*)(g + (size_t)r * ld + c);
        uint4 t;
        t.x = f2tf(v.x); t.y = f2tf(v.y); t.z = f2tf(v.z); t.w = f2tf(v.w);
        *(uint4*)(sm + r * LDP + c) = t;
    }
}

// ---------------------------------------------------------------------------
// boxtab_k: per-box sin/cos tables for the separable dw/dh embedding dims.
// ---------------------------------------------------------------------------
__global__ void boxtab_k(const float4* __restrict__ box,
                         const float4* __restrict__ ctx_box)
{
    int i = blockIdx.x * 128 + threadIdx.x;
    float4 Bx; float* dst;
    if (i < M_GT) { Bx = box[i]; dst = g_tabA + (size_t)i * 36; }
    else if (i < M_GT + N_CTX) { Bx = ctx_box[i - M_GT]; dst = g_tabB + (size_t)(i - M_GT) * 36; }
    else return;
    float lw = 100.0f * __logf(Bx.z - Bx.x + 1.0f);
    float lh = 100.0f * __logf(Bx.w - Bx.y + 1.0f);
#pragma unroll
    for (int j = 0; j < 8; j++) {
        float s, c;
        __sincosf(lw * c_invdim[j], &s, &c);
        dst[2 * j] = s; dst[2 * j + 1] = c;
        __sincosf(lh * c_invdim[j], &s, &c);
        dst[16 + 2 * j] = s; dst[17 + 2 * j] = c;
    }
}

// ---------------------------------------------------------------------------
// proj_mma: C = A @ W^T (+bias along N). 128x128 tiles, K=1024.
// ---------------------------------------------------------------------------
#define PROJ_BUF (128 * LDP * 2)

__global__ __launch_bounds__(256, 2) void proj_mma(
    const float* __restrict__ feat, const float* __restrict__ ctx_feat,
    const float* __restrict__ w_gt, const float* __restrict__ b_gt,
    const float* __restrict__ w_ctx, const float* __restrict__ b_ctx,
    const float* __restrict__ w_conv)
{
    const float* A; const float* W; const float* bias; float* C;
    int Mrows, Ncols;
    switch (blockIdx.z) {
    case 0:  A = feat;   W = w_gt;     bias = b_gt;  C = g_Q;  Mrows = M_GT;  Ncols = FEAT;  break;
    case 1:  A = ctx_feat; W = w_ctx;  bias = b_ctx; C = g_K;  Mrows = N_CTX; Ncols = FEAT;  break;
    case 2:  A = w_conv; W = feat;     bias = 0;     C = g_Ut; Mrows = FEAT;  Ncols = M_GT;  break;
    default: A = w_conv; W = ctx_feat; bias = 0;     C = g_Vt; Mrows = FEAT;  Ncols = N_CTX; break;
    }
    int bm = blockIdx.y * 128, bn = blockIdx.x * 128;
    if (bm >= Mrows || bn >= Ncols) return;

    extern __shared__ float dsm[];
    uint32_t smb = (uint32_t)__cvta_generic_to_shared(dsm);

    int tid = threadIdx.x, wid = tid >> 5, lane = tid & 31;
    int g4 = lane >> 2, tig = lane & 3;
    int wm = (wid & 1) * 64, wn = (wid >> 1) * 32;

    float acc[4][4][4];
#pragma unroll
    for (int i = 0; i < 4; i++)
#pragma unroll
        for (int j = 0; j < 4; j++)
#pragma unroll
            for (int q = 0; q < 4; q++) acc[i][j][q] = 0.0f;

    const float* Ab = A + (size_t)bm * FEAT;
    const float* Wb = W + (size_t)bn * FEAT;

    issue_chunk<128>(Ab, FEAT, smb, tid);
    issue_chunk<128>(Wb, FEAT, smb + 128 * LDP * 4u, tid);
    CP_COMMIT();

    const int NCH = FEAT / 32;
    for (int ch = 0; ch < NCH; ch++) {
        int buf = ch & 1;
        if (ch + 1 < NCH) {
            uint32_t nb = smb + (uint32_t)((ch + 1) & 1) * PROJ_BUF * 4u;
            issue_chunk<128>(Ab + (ch + 1) * 32, FEAT, nb, tid);
            issue_chunk<128>(Wb + (ch + 1) * 32, FEAT, nb + 128 * LDP * 4u, tid);
            CP_COMMIT();
            CP_WAIT1();
        } else {
            CP_WAIT0();
        }
        __syncthreads();
        const float* As = dsm + buf * PROJ_BUF;
        const float* Bs = As + 128 * LDP;
#pragma unroll
        for (int kk = 0; kk < 4; kk++) {
            int k0 = kk * 8 + tig;
            uint32_t bf[4][2];
#pragma unroll
            for (int j = 0; j < 4; j++) {
                int rn = (wn + j * 8 + g4) * LDP;
                bf[j][0] = f2tf(Bs[rn + k0]);
                bf[j][1] = f2tf(Bs[rn + k0 + 4]);
            }
#pragma unroll
            for (int i = 0; i < 4; i++) {
                int r0 = (wm + i * 16 + g4) * LDP;
                uint32_t af[4];
                af[0] = f2tf(As[r0 + k0]);
                af[1] = f2tf(As[r0 + 8 * LDP + k0]);
                af[2] = f2tf(As[r0 + k0 + 4]);
                af[3] = f2tf(As[r0 + 8 * LDP + k0 + 4]);
#pragma unroll
                for (int j = 0; j < 4; j++) mma8(acc[i][j], af, bf[j]);
            }
        }
        __syncthreads();
    }

#pragma unroll
    for (int i = 0; i < 4; i++) {
        int row = bm + wm + i * 16 + g4;
#pragma unroll
        for (int j = 0; j < 4; j++) {
            int col = bn + wn + j * 8 + 2 * tig;
            float b0 = bias ? bias[col] : 0.0f;
            float b1 = bias ? bias[col + 1] : 0.0f;
            float2 o0, o1;
            o0.x = acc[i][j][0] + b0; o0.y = acc[i][j][1] + b1;
            o1.x = acc[i][j][2] + b0; o1.y = acc[i][j][3] + b1;
            *(float2*)(C + (size_t)row * Ncols + col)       = o0;
            *(float2*)(C + (size_t)(row + 8) * Ncols + col) = o1;
        }
    }
}

// ---------------------------------------------------------------------------
// scores_mma: E[g,m,n] = exp(0.125 * Q.K) ; Et[g,n,m] via smem transpose.
// ---------------------------------------------------------------------------
#define TP 68

__global__ __launch_bounds__(256, 2) void scores_mma()
{
    int g = blockIdx.z;
    int bm = blockIdx.y * 128, bn = blockIdx.x * 128;
    const float* A = g_Q + (size_t)bm * FEAT + g * DK;
    const float* B = g_K + (size_t)bn * FEAT + g * DK;
    float* C  = g_E  + (size_t)g * MN;
    float* Ct = g_Et + (size_t)g * MN;

    __shared__ __align__(16) uint32_t sbuf[2 * 128 * LDP];
    uint32_t* As = sbuf;
    uint32_t* Bs = sbuf + 128 * LDP;
    float* T = (float*)sbuf;

    int tid = threadIdx.x, wid = tid >> 5, lane = tid & 31;
    int g4 = lane >> 2, tig = lane & 3;
    int wm = (wid & 1) * 64, wn = (wid >> 1) * 32;

    float acc[4][4][4];
#pragma unroll
    for (int i = 0; i < 4; i++)
#pragma unroll
        for (int j = 0; j < 4; j++)
#pragma unroll
            for (int q = 0; q < 4; q++) acc[i][j][q] = 0.0f;

    for (int ch = 0; ch < 2; ch++) {
        stage<128>(A + ch * 32, FEAT, As, tid);
        stage<128>(B + ch * 32, FEAT, Bs, tid);
        __syncthreads();
#pragma unroll
        for (int kk = 0; kk < 4; kk++) {
            int k0 = kk * 8 + tig;
            uint32_t bf[4][2];
#pragma unroll
            for (int j = 0; j < 4; j++) {
                int rn = (wn + j * 8 + g4) * LDP;
                bf[j][0] = Bs[rn + k0];
                bf[j][1] = Bs[rn + k0 + 4];
            }
#pragma unroll
            for (int i = 0; i < 4; i++) {
                int r0 = (wm + i * 16 + g4) * LDP;
                uint32_t af[4];
                af[0] = As[r0 + k0];
                af[1] = As[r0 + 8 * LDP + k0];
                af[2] = As[r0 + k0 + 4];
                af[3] = As[r0 + 8 * LDP + k0 + 4];
#pragma unroll
                for (int j = 0; j < 4; j++) mma8(acc[i][j], af, bf[j]);
            }
        }
        __syncthreads();
    }

    // exp once, in registers
#pragma unroll
    for (int i = 0; i < 4; i++)
#pragma unroll
        for (int j = 0; j < 4; j++)
#pragma unroll
            for (int q = 0; q < 4; q++)
                acc[i][j][q] = __expf(acc[i][j][q] * 0.125f);

#pragma unroll
    for (int i = 0; i < 4; i++) {
        int row = bm + wm + i * 16 + g4;
#pragma unroll
        for (int j = 0; j < 4; j++) {
            int col = bn + wn + j * 8 + 2 * tig;
            float2 o0, o1;
            o0.x = acc[i][j][0]; o0.y = acc[i][j][1];
            o1.x = acc[i][j][2]; o1.y = acc[i][j][3];
            *(float2*)(C + (size_t)row * N_CTX + col)       = o0;
            *(float2*)(C + (size_t)(row + 8) * N_CTX + col) = o1;
        }
    }

    for (int hh = 0; hh < 2; hh++) {
        __syncthreads();
        if ((wid & 1) == hh) {
#pragma unroll
            for (int i = 0; i < 4; i++) {
                int rl = i * 16 + g4;
#pragma unroll
                for (int j = 0; j < 4; j++) {
                    int col = wn + j * 8 + 2 * tig;
                    T[col * TP + rl]            = acc[i][j][0];
                    T[(col + 1) * TP + rl]      = acc[i][j][1];
                    T[col * TP + rl + 8]        = acc[i][j][2];
                    T[(col + 1) * TP + rl + 8]  = acc[i][j][3];
                }
            }
        }
        __syncthreads();
        int col = tid >> 1, seg = (tid & 1) << 5;
        const float* src = T + col * TP + seg;
        float* dst = Ct + (size_t)(bn + col) * M_GT + bm + hh * 64 + seg;
#pragma unroll
        for (int k = 0; k < 8; k++)
            *(float4*)(dst + k * 4) = *(const float4*)(src + k * 4);
    }
}

// ---------------------------------------------------------------------------
// attn_mma: z 0..15 gt, z 16..31 ctx. 128x64 tiles, warp tile 64x16.
// ---------------------------------------------------------------------------
#define ATTN_BUF (128 * LDP + 64 * LDP)

__global__ __launch_bounds__(256, 2) void attn_mma(
    const float* __restrict__ b_conv, float* __restrict__ out_gt,
    float* __restrict__ out_ctx)
{
    int z = blockIdx.z;
    int g = z & 15;
    bool gt = z < 16;
    const float* A = gt ? g_L1 + (size_t)g * MN : g_L2 + (size_t)g * MN;
    const float* B = gt ? g_Vt + (size_t)(g * DK) * N_CTX
                        : g_Ut + (size_t)(g * DK) * M_GT;
    float* C  = gt ? out_gt : out_ctx;
    int Mrows = gt ? M_GT : N_CTX;
    int Ktot  = gt ? N_CTX : M_GT;
    int bm = blockIdx.y * 128;
    if (bm >= Mrows) return;

    extern __shared__ float dsm[];
    uint32_t smb = (uint32_t)__cvta_generic_to_shared(dsm);

    int tid = threadIdx.x, wid = tid >> 5, lane = tid & 31;
    int g4 = lane >> 2, tig = lane & 3;
    int wm = (wid & 1) * 64, wn = (wid >> 1) * 16;

    float acc[4][2][4];
#pragma unroll
    for (int i = 0; i < 4; i++)
#pragma unroll
        for (int j = 0; j < 2; j++)
#pragma unroll
            for (int q = 0; q < 4; q++) acc[i][j][q] = 0.0f;

    const float* Ab = A + (size_t)bm * Ktot;

    issue_chunk<128>(Ab, Ktot, smb, tid);
    issue_chunk<64>(B, Ktot, smb + 128 * LDP * 4u, tid);
    CP_COMMIT();

    int NCH = Ktot / 32;
    for (int ch = 0; ch < NCH; ch++) {
        int buf = ch & 1;
        if (ch + 1 < NCH) {
            uint32_t nb = smb + (uint32_t)((ch + 1) & 1) * ATTN_BUF * 4u;
            issue_chunk<128>(Ab + (ch + 1) * 32, Ktot, nb, tid);
            issue_chunk<64>(B + (ch + 1) * 32, Ktot, nb + 128 * LDP * 4u, tid);
            CP_COMMIT();
            CP_WAIT1();
        } else {
            CP_WAIT0();
        }
        __syncthreads();
        const float* As = dsm + buf * ATTN_BUF;
        const float* Bs = As + 128 * LDP;
#pragma unroll
        for (int kk = 0; kk < 4; kk++) {
            int k0 = kk * 8 + tig;
            uint32_t bf[2][2];
#pragma unroll
            for (int j = 0; j < 2; j++) {
                int rn = (wn + j * 8 + g4) * LDP;
                bf[j][0] = f2tf(Bs[rn + k0]);
                bf[j][1] = f2tf(Bs[rn + k0 + 4]);
            }
#pragma unroll
            for (int i = 0; i < 4; i++) {
                int r0 = (wm + i * 16 + g4) * LDP;
                uint32_t af[4];
                af[0] = f2tf(As[r0 + k0]);
                af[1] = f2tf(As[r0 + 8 * LDP + k0]);
                af[2] = f2tf(As[r0 + k0 + 4]);
                af[3] = f2tf(As[r0 + 8 * LDP + k0 + 4]);
#pragma unroll
                for (int j = 0; j < 2; j++) mma8(acc[i][j], af, bf[j]);
            }
        }
        __syncthreads();
    }

#pragma unroll
    for (int i = 0; i < 4; i++) {
        int row = bm + wm + i * 16 + g4;
#pragma unroll
        for (int j = 0; j < 2; j++) {
            int col = g * DK + wn + j * 8 + 2 * tig;
            float b0 = b_conv[col], b1 = b_conv[col + 1];
            float2 o0, o1;
            o0.x = acc[i][j][0] + b0; o0.y = acc[i][j][1] + b1;
            o1.x = acc[i][j][2] + b0; o1.y = acc[i][j][3] + b1;
            *(float2*)(C + (size_t)row * FEAT + col)       = o0;
            *(float2*)(C + (size_t)(row + 8) * FEAT + col) = o1;
        }
    }
}

// ---------------------------------------------------------------------------
// pos_soft<NCOLS>: fused pos-embedding + exp-weight product + normalization.
// weights[g,r,c] = max(pos(r,c,g)+b[g], 1e-6) * E[g,r,c] / rowsum.
// NO log, NO exp, NO max pass (softmax identity: softmax(log p + s) =
// p*exp(s)/sum). Tensor-core pos-linear with 3-term tf32 hi/lo split.
// ---------------------------------------------------------------------------
template <int NCOLS>
__global__ __launch_bounds__(NCOLS / 4, 512 / (NCOLS / 4)) void pos_soft(
    const float4* __restrict__ boxA, const float4* __restrict__ boxB,
    const float* __restrict__ tabA, const float* __restrict__ tabB,
    const float* __restrict__ w_pos, const float* __restrict__ b_pos,
    const float* __restrict__ Eb, float* __restrict__ L)
{
    constexpr int NT = NCOLS / 4;
    constexpr int NW = NT / 32;
    constexpr int SLP = NCOLS + 4;            // smem pitch
    extern __shared__ float sl[];             // [NG][SLP]
    __shared__ float wbh[16 * 68];            // w_pos tf32-hi, pitch 68
    __shared__ float wbl[16 * 68];            // w_pos tf32-lo
    __shared__ float bp[NG];
    __shared__ float rbuf[NG * (NW + 1)];

    int tid = threadIdx.x, wid = tid >> 5, lane = tid & 31;
    int g4 = lane >> 2, tig = lane & 3;

    for (int i = tid; i < 1024; i += NT) {
        int g = i >> 6, f = i & 63;
        float w = w_pos[i];
        uint32_t hb = f2tf(w);
        float hf = __uint_as_float(hb);
        wbh[g * 68 + f] = hf;
        wbl[g * 68 + f] = __uint_as_float(f2tf(w - hf));
    }
    if (tid < NG) bp[tid] = b_pos[tid];
    __syncthreads();

    int r = blockIdx.x;
    float4 A = boxA[r];
    float bw = A.z - A.x + 1.0f, bh = A.w - A.y + 1.0f;
    float cx = 0.5f * (A.x + A.z), cy = 0.5f * (A.y + A.w);
    float rbw = 1.0f / bw, rbh = 1.0f / bh;
    float ivA = c_invdim[tig], ivB = c_invdim[tig + 4];

    const float* tr = tabA + (size_t)r * 36;
    float2 rw0 = *(const float2*)(tr + 2 * tig);
    float2 rw1 = *(const float2*)(tr + 2 * tig + 8);
    float2 rh0 = *(const float2*)(tr + 16 + 2 * tig);
    float2 rh1 = *(const float2*)(tr + 24 + 2 * tig);

    for (int mt = 0; mt < 8; mt++) {
        int base = wid * 128 + mt * 16;
        float a[2][8][2];   // [col ci][kk][k-half]
#pragma unroll
        for (int ci = 0; ci < 2; ci++) {
            int col = base + ci * 8 + g4;
            float4 Bx = boxB[col];
            float p0 = 100.0f * __logf(fmaxf(fabsf((cx - 0.5f * (Bx.x + Bx.z)) * rbw), 1e-3f));
            float p1 = 100.0f * __logf(fmaxf(fabsf((cy - 0.5f * (Bx.y + Bx.w)) * rbh), 1e-3f));
            float s, c;
            __sincosf(p0 * ivA, &s, &c);
            a[ci][0][0] = fmaxf(s, 0.0f); a[ci][1][0] = fmaxf(c, 0.0f);
            __sincosf(p0 * ivB, &s, &c);
            a[ci][0][1] = fmaxf(s, 0.0f); a[ci][1][1] = fmaxf(c, 0.0f);
            __sincosf(p1 * ivA, &s, &c);
            a[ci][2][0] = fmaxf(s, 0.0f); a[ci][3][0] = fmaxf(c, 0.0f);
            __sincosf(p1 * ivB, &s, &c);
            a[ci][2][1] = fmaxf(s, 0.0f); a[ci][3][1] = fmaxf(c, 0.0f);
            const float* tc = tabB + (size_t)col * 36;
            float2 cw0 = *(const float2*)(tc + 2 * tig);
            float2 cw1 = *(const float2*)(tc + 2 * tig + 8);
            float2 ch0 = *(const float2*)(tc + 16 + 2 * tig);
            float2 ch1 = *(const float2*)(tc + 24 + 2 * tig);
            a[ci][4][0] = fmaxf(cw0.x * rw0.y - cw0.y * rw0.x, 0.0f);
            a[ci][4][1] = fmaxf(cw1.x * rw1.y - cw1.y * rw1.x, 0.0f);
            a[ci][5][0] = fmaxf(cw0.y * rw0.y + cw0.x * rw0.x, 0.0f);
            a[ci][5][1] = fmaxf(cw1.y * rw1.y + cw1.x * rw1.x, 0.0f);
            a[ci][6][0] = fmaxf(ch0.x * rh0.y - ch0.y * rh0.x, 0.0f);
            a[ci][6][1] = fmaxf(ch1.x * rh1.y - ch1.y * rh1.x, 0.0f);
            a[ci][7][0] = fmaxf(ch0.y * rh0.y + ch0.x * rh0.x, 0.0f);
            a[ci][7][1] = fmaxf(ch1.y * rh1.y + ch1.x * rh1.x, 0.0f);
        }

        float acc[2][4];
#pragma unroll
        for (int j = 0; j < 2; j++)
#pragma unroll
            for (int q = 0; q < 4; q++) acc[j][q] = 0.0f;

#pragma unroll
        for (int kk = 0; kk < 8; kk++) {
            uint32_t ah[4], al[4];
#pragma unroll
            for (int q = 0; q < 4; q++) {
                float v = a[q & 1][kk][q >> 1];
                uint32_t h = f2tf(v);
                ah[q] = h;
                al[q] = f2tf(v - __uint_as_float(h));
            }
            int ko = 8 * kk + tig;
#pragma unroll
            for (int j = 0; j < 2; j++) {
                int rb = (8 * j + g4) * 68 + ko;
                uint32_t bh2[2], bl2[2];
                bh2[0] = __float_as_uint(wbh[rb]);
                bh2[1] = __float_as_uint(wbh[rb + 4]);
                bl2[0] = __float_as_uint(wbl[rb]);
                bl2[1] = __float_as_uint(wbl[rb + 4]);
                mma8(acc[j], ah, bh2);
                mma8(acc[j], ah, bl2);
                mma8(acc[j], al, bh2);
            }
        }

        int cA = base + g4, cB = cA + 8;
#pragma unroll
        for (int j = 0; j < 2; j++) {
            int ga = 8 * j + 2 * tig, gb = ga + 1;
            sl[ga * SLP + cA] = fmaxf(acc[j][0] + bp[ga], 1e-6f);
            sl[gb * SLP + cA] = fmaxf(acc[j][1] + bp[gb], 1e-6f);
            sl[ga * SLP + cB] = fmaxf(acc[j][2] + bp[ga], 1e-6f);
            sl[gb * SLP + cB] = fmaxf(acc[j][3] + bp[gb], 1e-6f);
        }
    }
    __syncthreads();

    // ---- phase 2: multiply by exp(scores) (coalesced) + sum-normalize ----
    int c0 = tid * 4;
    size_t sro = (size_t)r * NCOLS + c0;
    float sum[NG];
#pragma unroll
    for (int g = 0; g < NG; g++) {
        float4 v = *(float4*)&sl[g * SLP + c0];
        float4 e = *(const float4*)(Eb + (size_t)g * MN + sro);
        v.x *= e.x; v.y *= e.y; v.z *= e.z; v.w *= e.w;
        *(float4*)&sl[g * SLP + c0] = v;
        sum[g] = (v.x + v.y) + (v.z + v.w);
    }
#pragma unroll
    for (int g = 0; g < NG; g++) {
#pragma unroll
        for (int o = 16; o; o >>= 1)
            sum[g] += __shfl_xor_sync(0xffffffffu, sum[g], o);
    }
    if (lane == 0) {
#pragma unroll
        for (int g = 0; g < NG; g++) rbuf[g * (NW + 1) + wid] = sum[g];
    }
    __syncthreads();
    if (tid < NG) {
        float t = 0.0f;
#pragma unroll
        for (int w = 0; w < NW; w++) t += rbuf[tid * (NW + 1) + w];
        rbuf[tid * (NW + 1) + NW] = t;
    }
    __syncthreads();

#pragma unroll
    for (int g = 0; g < NG; g++) {
        float inv = __frcp_rn(rbuf[g * (NW + 1) + NW]);
        float4 v = *(float4*)&sl[g * SLP + c0];
        v.x *= inv; v.y *= inv; v.z *= inv; v.w *= inv;
        *(float4*)(L + (size_t)g * MN + (size_t)r * NCOLS + c0) = v;
    }
}

// ---------------------------------------------------------------------------
extern "C" void kernel_launch(void* const* d_in, const int* in_sizes, int n_in,
                              void* d_out, int out_size)
{
    (void)in_sizes; (void)n_in; (void)out_size;
    const float* feat      = (const float*)d_in[0];
    const float* ctx_feat  = (const float*)d_in[1];
    const float* box       = (const float*)d_in[2];
    const float* ctx_box   = (const float*)d_in[3];
    const float* w_fc_gt   = (const float*)d_in[4];
    const float* b_fc_gt   = (const float*)d_in[5];
    const float* w_fc_ctx  = (const float*)d_in[6];
    const float* b_fc_ctx  = (const float*)d_in[7];
    const float* w_pos_gt  = (const float*)d_in[8];
    const float* b_pos_gt  = (const float*)d_in[9];
    const float* w_pos_ctx = (const float*)d_in[10];
    const float* b_pos_ctx = (const float*)d_in[11];
    const float* w_conv    = (const float*)d_in[12];
    const float* b_conv    = (const float*)d_in[13];

    float* out = (float*)d_out;
    float* out_gt  = out;
    float* out_ctx = out + (size_t)M_GT * FEAT;

    float *E, *Et, *L1, *L2, *tabA, *tabB;
    cudaGetSymbolAddress((void**)&E,    g_E);
    cudaGetSymbolAddress((void**)&Et,   g_Et);
    cudaGetSymbolAddress((void**)&L1,   g_L1);
    cudaGetSymbolAddress((void**)&L2,   g_L2);
    cudaGetSymbolAddress((void**)&tabA, g_tabA);
    cudaGetSymbolAddress((void**)&tabB, g_tabB);

    static int attr_done = 0;
    if (!attr_done) {
        cudaFuncSetAttribute(proj_mma, cudaFuncAttributeMaxDynamicSharedMemorySize,
                             2 * PROJ_BUF * 4);
        cudaFuncSetAttribute(attn_mma, cudaFuncAttributeMaxDynamicSharedMemorySize,
                             2 * ATTN_BUF * 4);
        cudaFuncSetAttribute(pos_soft<N_CTX>, cudaFuncAttributeMaxDynamicSharedMemorySize,
                             NG * (N_CTX + 4) * 4);
        cudaFuncSetAttribute(pos_soft<M_GT>, cudaFuncAttributeMaxDynamicSharedMemorySize,
                             NG * (M_GT + 4) * 4);
        attr_done = 1;
    }

    // 0) per-box sin/cos tables
    boxtab_k<<<(M_GT + N_CTX + 127) / 128, 128>>>((const float4*)box,
                                                  (const float4*)ctx_box);
    // 1) Q, K, Ut, Vt projections
    proj_mma<<<dim3(8, 8, 4), 256, 2 * PROJ_BUF * 4>>>(
        feat, ctx_feat, w_fc_gt, b_fc_gt, w_fc_ctx, b_fc_ctx, w_conv);
    // 2) E = exp(scores), E + Et
    scores_mma<<<dim3(8, 4, 16), 256>>>();
    // 3) fused pos-embedding + exp-weight + normalize
    pos_soft<N_CTX><<<M_GT, N_CTX / 4, NG * (N_CTX + 4) * 4>>>(
        (const float4*)box, (const float4*)ctx_box, tabA, tabB,
        w_pos_gt, b_pos_gt, E, L1);
    pos_soft<M_GT><<<N_CTX, M_GT / 4, NG * (M_GT + 4) * 4>>>(
        (const float4*)ctx_box, (const float4*)box, tabB, tabA,
        w_pos_ctx, b_pos_ctx, Et, L2);
    // 4) attention output
    attn_mma<<<dim3(1, 8, 32), 256, 2 * ATTN_BUF * 4>>>(b_conv, out_gt, out_ctx);
}

// round 15
// speedup vs baseline: 1.0498x; 1.0077x over previous
#include <cuda_runtime.h>
#include <cstdint>

#define M_GT  512
#define N_CTX 1024
#define FEAT  1024
#define NG    16
#define DK    64
#define MN    (M_GT * N_CTX)   // 524288

// ---------------- device scratch (static globals; no allocation) ------------
// Q/K/Ut/Vt/L1/L2 hold tf32-rounded values (producers round; consumers load raw)
__device__ float g_Q [M_GT * FEAT];
__device__ float g_K [N_CTX * FEAT];
__device__ float g_Ut[FEAT * M_GT];    // Ut[o][m]
__device__ float g_Vt[FEAT * N_CTX];   // Vt[o][n]
__device__ float g_E [NG * MN];        // exp(scores)  (G, M, N)
__device__ float g_Et[NG * MN];        // exp(scores)^T (G, N, M)
__device__ float g_L1[NG * MN];        // weights gt  (G, M, N)
__device__ float g_L2[NG * MN];        // weights ctx (G, N, M)
__device__ float g_tabA[M_GT * 36];    // per-box sin/cos tables (gt boxes)
__device__ float g_tabB[N_CTX * 36];   // per-box sin/cos tables (ctx boxes)

// 1000^(-j/8)
__constant__ float c_invdim[8] = {
    1.0f, 0.4216965034f, 0.1778279410f, 0.0749894209f,
    0.0316227766f, 0.0133352143f, 0.0056234133f, 0.0023713737f
};

// ======================= helpers ==========================
__device__ __forceinline__ uint32_t f2tf(float x) {
    uint32_t r;
    asm("cvt.rna.tf32.f32 %0, %1;" : "=r"(r) : "f"(x));
    return r;
}
__device__ __forceinline__ float f2tff(float x) {
    return __uint_as_float(f2tf(x));
}

__device__ __forceinline__ void mma8(float* c, const uint32_t* a, const uint32_t* b) {
    asm volatile(
        "mma.sync.aligned.m16n8k8.row.col.f32.tf32.tf32.f32 "
        "{%0,%1,%2,%3}, {%4,%5,%6,%7}, {%8,%9}, {%0,%1,%2,%3};"
        : "+f"(c[0]), "+f"(c[1]), "+f"(c[2]), "+f"(c[3])
        : "r"(a[0]), "r"(a[1]), "r"(a[2]), "r"(a[3]), "r"(b[0]), "r"(b[1]));
}

__device__ __forceinline__ void cp16(uint32_t s, const void* g) {
    asm volatile("cp.async.cg.shared.global [%0], [%1], 16;" :: "r"(s), "l"(g));
}
#define CP_COMMIT() asm volatile("cp.async.commit_group;" ::: "memory")
#define CP_WAIT1()  asm volatile("cp.async.wait_group 1;" ::: "memory")
#define CP_WAIT0()  asm volatile("cp.async.wait_group 0;" ::: "memory")

#define LDP 36   // smem row pitch (floats)

template <int ROWS>
__device__ __forceinline__ void issue_chunk(const float* __restrict__ g, int ld,
                                            uint32_t smbase, int tid)
{
#pragma unroll
    for (int i = 0; i < ROWS / 32; i++) {
        int idx = tid + i * 256;
        int r = idx >> 3, c = (idx & 7) << 2;
        cp16(smbase + (uint32_t)(r * LDP + c) * 4u, g + (size_t)r * ld + c);
    }
}

// raw staging (values already tf32-rounded by producer)
template <int ROWS>
__device__ __forceinline__ void stage_raw(const float* __restrict__ g, int ld,
                                          uint32_t* __restrict__ sm, int tid)
{
#pragma unroll
    for (int i = 0; i < ROWS / 32; i++) {
        int idx = tid + i * 256;
        int r = idx >> 3, c = (idx & 7) << 2;
        uint4 v = *(const uint4*)(g + (size_t)r * ld + c);
        *(uint4*)(sm + r * LDP + c) = v;
    }
}

// ---------------------------------------------------------------------------
// boxtab_k: per-box sin/cos tables for the separable dw/dh embedding dims.
// ---------------------------------------------------------------------------
__global__ void boxtab_k(const float4* __restrict__ box,
                         const float4* __restrict__ ctx_box)
{
    int i = blockIdx.x * 128 + threadIdx.x;
    float4 Bx; float* dst;
    if (i < M_GT) { Bx = box[i]; dst = g_tabA + (size_t)i * 36; }
    else if (i < M_GT + N_CTX) { Bx = ctx_box[i - M_GT]; dst = g_tabB + (size_t)(i - M_GT) * 36; }
    else return;
    float lw = 100.0f * __logf(Bx.z - Bx.x + 1.0f);
    float lh = 100.0f * __logf(Bx.w - Bx.y + 1.0f);
#pragma unroll
    for (int j = 0; j < 8; j++) {
        float s, c;
        __sincosf(lw * c_invdim[j], &s, &c);
        dst[2 * j] = s; dst[2 * j + 1] = c;
        __sincosf(lh * c_invdim[j], &s, &c);
        dst[16 + 2 * j] = s; dst[17 + 2 * j] = c;
    }
}

// ---------------------------------------------------------------------------
// proj_mma: C = tf32_round(A @ W^T (+bias)). 128x128 tiles, K=1024.
// ---------------------------------------------------------------------------
#define PROJ_BUF (128 * LDP * 2)

__global__ __launch_bounds__(256, 2) void proj_mma(
    const float* __restrict__ feat, const float* __restrict__ ctx_feat,
    const float* __restrict__ w_gt, const float* __restrict__ b_gt,
    const float* __restrict__ w_ctx, const float* __restrict__ b_ctx,
    const float* __restrict__ w_conv)
{
    const float* A; const float* W; const float* bias; float* C;
    int Mrows, Ncols;
    switch (blockIdx.z) {
    case 0:  A = feat;   W = w_gt;     bias = b_gt;  C = g_Q;  Mrows = M_GT;  Ncols = FEAT;  break;
    case 1:  A = ctx_feat; W = w_ctx;  bias = b_ctx; C = g_K;  Mrows = N_CTX; Ncols = FEAT;  break;
    case 2:  A = w_conv; W = feat;     bias = 0;     C = g_Ut; Mrows = FEAT;  Ncols = M_GT;  break;
    default: A = w_conv; W = ctx_feat; bias = 0;     C = g_Vt; Mrows = FEAT;  Ncols = N_CTX; break;
    }
    int bm = blockIdx.y * 128, bn = blockIdx.x * 128;
    if (bm >= Mrows || bn >= Ncols) return;

    extern __shared__ float dsm[];
    uint32_t smb = (uint32_t)__cvta_generic_to_shared(dsm);

    int tid = threadIdx.x, wid = tid >> 5, lane = tid & 31;
    int g4 = lane >> 2, tig = lane & 3;
    int wm = (wid & 1) * 64, wn = (wid >> 1) * 32;

    float acc[4][4][4];
#pragma unroll
    for (int i = 0; i < 4; i++)
#pragma unroll
        for (int j = 0; j < 4; j++)
#pragma unroll
            for (int q = 0; q < 4; q++) acc[i][j][q] = 0.0f;

    const float* Ab = A + (size_t)bm * FEAT;
    const float* Wb = W + (size_t)bn * FEAT;

    issue_chunk<128>(Ab, FEAT, smb, tid);
    issue_chunk<128>(Wb, FEAT, smb + 128 * LDP * 4u, tid);
    CP_COMMIT();

    const int NCH = FEAT / 32;
    for (int ch = 0; ch < NCH; ch++) {
        int buf = ch & 1;
        if (ch + 1 < NCH) {
            uint32_t nb = smb + (uint32_t)((ch + 1) & 1) * PROJ_BUF * 4u;
            issue_chunk<128>(Ab + (ch + 1) * 32, FEAT, nb, tid);
            issue_chunk<128>(Wb + (ch + 1) * 32, FEAT, nb + 128 * LDP * 4u, tid);
            CP_COMMIT();
            CP_WAIT1();
        } else {
            CP_WAIT0();
        }
        __syncthreads();
        const float* As = dsm + buf * PROJ_BUF;
        const float* Bs = As + 128 * LDP;
#pragma unroll
        for (int kk = 0; kk < 4; kk++) {
            int k0 = kk * 8 + tig;
            uint32_t bf[4][2];
#pragma unroll
            for (int j = 0; j < 4; j++) {
                int rn = (wn + j * 8 + g4) * LDP;
                bf[j][0] = f2tf(Bs[rn + k0]);
                bf[j][1] = f2tf(Bs[rn + k0 + 4]);
            }
#pragma unroll
            for (int i = 0; i < 4; i++) {
                int r0 = (wm + i * 16 + g4) * LDP;
                uint32_t af[4];
                af[0] = f2tf(As[r0 + k0]);
                af[1] = f2tf(As[r0 + 8 * LDP + k0]);
                af[2] = f2tf(As[r0 + k0 + 4]);
                af[3] = f2tf(As[r0 + 8 * LDP + k0 + 4]);
#pragma unroll
                for (int j = 0; j < 4; j++) mma8(acc[i][j], af, bf[j]);
            }
        }
        __syncthreads();
    }

#pragma unroll
    for (int i = 0; i < 4; i++) {
        int row = bm + wm + i * 16 + g4;
#pragma unroll
        for (int j = 0; j < 4; j++) {
            int col = bn + wn + j * 8 + 2 * tig;
            float b0 = bias ? bias[col] : 0.0f;
            float b1 = bias ? bias[col + 1] : 0.0f;
            float2 o0, o1;
            o0.x = f2tff(acc[i][j][0] + b0); o0.y = f2tff(acc[i][j][1] + b1);
            o1.x = f2tff(acc[i][j][2] + b0); o1.y = f2tff(acc[i][j][3] + b1);
            *(float2*)(C + (size_t)row * Ncols + col)       = o0;
            *(float2*)(C + (size_t)(row + 8) * Ncols + col) = o1;
        }
    }
}

// ---------------------------------------------------------------------------
// scores_mma: E[g,m,n] = exp(0.125 * Q.K) ; Et[g,n,m] via smem transpose.
// Q/K already tf32-rounded -> raw staging, no cvt.
// ---------------------------------------------------------------------------
#define TP 68

__global__ __launch_bounds__(256, 2) void scores_mma()
{
    int g = blockIdx.z;
    int bm = blockIdx.y * 128, bn = blockIdx.x * 128;
    const float* A = g_Q + (size_t)bm * FEAT + g * DK;
    const float* B = g_K + (size_t)bn * FEAT + g * DK;
    float* C  = g_E  + (size_t)g * MN;
    float* Ct = g_Et + (size_t)g * MN;

    __shared__ __align__(16) uint32_t sbuf[2 * 128 * LDP];
    uint32_t* As = sbuf;
    uint32_t* Bs = sbuf + 128 * LDP;
    float* T = (float*)sbuf;

    int tid = threadIdx.x, wid = tid >> 5, lane = tid & 31;
    int g4 = lane >> 2, tig = lane & 3;
    int wm = (wid & 1) * 64, wn = (wid >> 1) * 32;

    float acc[4][4][4];
#pragma unroll
    for (int i = 0; i < 4; i++)
#pragma unroll
        for (int j = 0; j < 4; j++)
#pragma unroll
            for (int q = 0; q < 4; q++) acc[i][j][q] = 0.0f;

    for (int ch = 0; ch < 2; ch++) {
        stage_raw<128>(A + ch * 32, FEAT, As, tid);
        stage_raw<128>(B + ch * 32, FEAT, Bs, tid);
        __syncthreads();
#pragma unroll
        for (int kk = 0; kk < 4; kk++) {
            int k0 = kk * 8 + tig;
            uint32_t bf[4][2];
#pragma unroll
            for (int j = 0; j < 4; j++) {
                int rn = (wn + j * 8 + g4) * LDP;
                bf[j][0] = Bs[rn + k0];
                bf[j][1] = Bs[rn + k0 + 4];
            }
#pragma unroll
            for (int i = 0; i < 4; i++) {
                int r0 = (wm + i * 16 + g4) * LDP;
                uint32_t af[4];
                af[0] = As[r0 + k0];
                af[1] = As[r0 + 8 * LDP + k0];
                af[2] = As[r0 + k0 + 4];
                af[3] = As[r0 + 8 * LDP + k0 + 4];
#pragma unroll
                for (int j = 0; j < 4; j++) mma8(acc[i][j], af, bf[j]);
            }
        }
        __syncthreads();
    }

    // exp once, in registers
#pragma unroll
    for (int i = 0; i < 4; i++)
#pragma unroll
        for (int j = 0; j < 4; j++)
#pragma unroll
            for (int q = 0; q < 4; q++)
                acc[i][j][q] = __expf(acc[i][j][q] * 0.125f);

#pragma unroll
    for (int i = 0; i < 4; i++) {
        int row = bm + wm + i * 16 + g4;
#pragma unroll
        for (int j = 0; j < 4; j++) {
            int col = bn + wn + j * 8 + 2 * tig;
            float2 o0, o1;
            o0.x = acc[i][j][0]; o0.y = acc[i][j][1];
            o1.x = acc[i][j][2]; o1.y = acc[i][j][3];
            *(float2*)(C + (size_t)row * N_CTX + col)       = o0;
            *(float2*)(C + (size_t)(row + 8) * N_CTX + col) = o1;
        }
    }

    for (int hh = 0; hh < 2; hh++) {
        __syncthreads();
        if ((wid & 1) == hh) {
#pragma unroll
            for (int i = 0; i < 4; i++) {
                int rl = i * 16 + g4;
#pragma unroll
                for (int j = 0; j < 4; j++) {
                    int col = wn + j * 8 + 2 * tig;
                    T[col * TP + rl]            = acc[i][j][0];
                    T[(col + 1) * TP + rl]      = acc[i][j][1];
                    T[col * TP + rl + 8]        = acc[i][j][2];
                    T[(col + 1) * TP + rl + 8]  = acc[i][j][3];
                }
            }
        }
        __syncthreads();
        int col = tid >> 1, seg = (tid & 1) << 5;
        const float* src = T + col * TP + seg;
        float* dst = Ct + (size_t)(bn + col) * M_GT + bm + hh * 64 + seg;
#pragma unroll
        for (int k = 0; k < 8; k++)
            *(float4*)(dst + k * 4) = *(const float4*)(src + k * 4);
    }
}

// ---------------------------------------------------------------------------
// attn_mma: z 0..15 gt, z 16..31 ctx. 128x64 tiles, warp tile 64x16.
// A (L) and B (Vt/Ut) already tf32-rounded -> raw fragment loads, no cvt.
// ---------------------------------------------------------------------------
#define ATTN_BUF (128 * LDP + 64 * LDP)

__global__ __launch_bounds__(256, 2) void attn_mma(
    const float* __restrict__ b_conv, float* __restrict__ out_gt,
    float* __restrict__ out_ctx)
{
    int z = blockIdx.z;
    int g = z & 15;
    bool gt = z < 16;
    const float* A = gt ? g_L1 + (size_t)g * MN : g_L2 + (size_t)g * MN;
    const float* B = gt ? g_Vt + (size_t)(g * DK) * N_CTX
                        : g_Ut + (size_t)(g * DK) * M_GT;
    float* C  = gt ? out_gt : out_ctx;
    int Mrows = gt ? M_GT : N_CTX;
    int Ktot  = gt ? N_CTX : M_GT;
    int bm = blockIdx.y * 128;
    if (bm >= Mrows) return;

    extern __shared__ float dsm[];
    uint32_t smb = (uint32_t)__cvta_generic_to_shared(dsm);

    int tid = threadIdx.x, wid = tid >> 5, lane = tid & 31;
    int g4 = lane >> 2, tig = lane & 3;
    int wm = (wid & 1) * 64, wn = (wid >> 1) * 16;

    float acc[4][2][4];
#pragma unroll
    for (int i = 0; i < 4; i++)
#pragma unroll
        for (int j = 0; j < 2; j++)
#pragma unroll
            for (int q = 0; q < 4; q++) acc[i][j][q] = 0.0f;

    const float* Ab = A + (size_t)bm * Ktot;

    issue_chunk<128>(Ab, Ktot, smb, tid);
    issue_chunk<64>(B, Ktot, smb + 128 * LDP * 4u, tid);
    CP_COMMIT();

    int NCH = Ktot / 32;
    for (int ch = 0; ch < NCH; ch++) {
        int buf = ch & 1;
        if (ch + 1 < NCH) {
            uint32_t nb = smb + (uint32_t)((ch + 1) & 1) * ATTN_BUF * 4u;
            issue_chunk<128>(Ab + (ch + 1) * 32, Ktot, nb, tid);
            issue_chunk<64>(B + (ch + 1) * 32, Ktot, nb + 128 * LDP * 4u, tid);
            CP_COMMIT();
            CP_WAIT1();
        } else {
            CP_WAIT0();
        }
        __syncthreads();
        const uint32_t* As = (const uint32_t*)(dsm + buf * ATTN_BUF);
        const uint32_t* Bs = As + 128 * LDP;
#pragma unroll
        for (int kk = 0; kk < 4; kk++) {
            int k0 = kk * 8 + tig;
            uint32_t bf[2][2];
#pragma unroll
            for (int j = 0; j < 2; j++) {
                int rn = (wn + j * 8 + g4) * LDP;
                bf[j][0] = Bs[rn + k0];
                bf[j][1] = Bs[rn + k0 + 4];
            }
#pragma unroll
            for (int i = 0; i < 4; i++) {
                int r0 = (wm + i * 16 + g4) * LDP;
                uint32_t af[4];
                af[0] = As[r0 + k0];
                af[1] = As[r0 + 8 * LDP + k0];
                af[2] = As[r0 + k0 + 4];
                af[3] = As[r0 + 8 * LDP + k0 + 4];
#pragma unroll
                for (int j = 0; j < 2; j++) mma8(acc[i][j], af, bf[j]);
            }
        }
        __syncthreads();
    }

#pragma unroll
    for (int i = 0; i < 4; i++) {
        int row = bm + wm + i * 16 + g4;
#pragma unroll
        for (int j = 0; j < 2; j++) {
            int col = g * DK + wn + j * 8 + 2 * tig;
            float b0 = b_conv[col], b1 = b_conv[col + 1];
            float2 o0, o1;
            o0.x = acc[i][j][0] + b0; o0.y = acc[i][j][1] + b1;
            o1.x = acc[i][j][2] + b0; o1.y = acc[i][j][3] + b1;
            *(float2*)(C + (size_t)row * FEAT + col)       = o0;
            *(float2*)(C + (size_t)(row + 8) * FEAT + col) = o1;
        }
    }
}

// ---------------------------------------------------------------------------
// pos_soft<NCOLS>: fused pos-embedding + exp-weight product + normalization.
// weights = tf32_round(max(pos+b,1e-6) * E / rowsum)  (attn loads raw bits).
// ---------------------------------------------------------------------------
template <int NCOLS>
__global__ __launch_bounds__(NCOLS / 4, 512 / (NCOLS / 4)) void pos_soft(
    const float4* __restrict__ boxA, const float4* __restrict__ boxB,
    const float* __restrict__ tabA, const float* __restrict__ tabB,
    const float* __restrict__ w_pos, const float* __restrict__ b_pos,
    const float* __restrict__ Eb, float* __restrict__ L)
{
    constexpr int NT = NCOLS / 4;
    constexpr int NW = NT / 32;
    constexpr int SLP = NCOLS + 4;            // smem pitch
    extern __shared__ float sl[];             // [NG][SLP]
    __shared__ float wbh[16 * 68];            // w_pos tf32-hi, pitch 68
    __shared__ float wbl[16 * 68];            // w_pos tf32-lo
    __shared__ float bp[NG];
    __shared__ float rbuf[NG * (NW + 1)];

    int tid = threadIdx.x, wid = tid >> 5, lane = tid & 31;
    int g4 = lane >> 2, tig = lane & 3;

    for (int i = tid; i < 1024; i += NT) {
        int g = i >> 6, f = i & 63;
        float w = w_pos[i];
        uint32_t hb = f2tf(w);
        float hf = __uint_as_float(hb);
        wbh[g * 68 + f] = hf;
        wbl[g * 68 + f] = __uint_as_float(f2tf(w - hf));
    }
    if (tid < NG) bp[tid] = b_pos[tid];
    __syncthreads();

    int r = blockIdx.x;
    float4 A = boxA[r];
    float bw = A.z - A.x + 1.0f, bh = A.w - A.y + 1.0f;
    float cx = 0.5f * (A.x + A.z), cy = 0.5f * (A.y + A.w);
    float rbw = 1.0f / bw, rbh = 1.0f / bh;
    float ivA = c_invdim[tig], ivB = c_invdim[tig + 4];

    const float* tr = tabA + (size_t)r * 36;
    float2 rw0 = *(const float2*)(tr + 2 * tig);
    float2 rw1 = *(const float2*)(tr + 2 * tig + 8);
    float2 rh0 = *(const float2*)(tr + 16 + 2 * tig);
    float2 rh1 = *(const float2*)(tr + 24 + 2 * tig);

    for (int mt = 0; mt < 8; mt++) {
        int base = wid * 128 + mt * 16;
        float a[2][8][2];   // [col ci][kk][k-half]
#pragma unroll
        for (int ci = 0; ci < 2; ci++) {
            int col = base + ci * 8 + g4;
            float4 Bx = boxB[col];
            float p0 = 100.0f * __logf(fmaxf(fabsf((cx - 0.5f * (Bx.x + Bx.z)) * rbw), 1e-3f));
            float p1 = 100.0f * __logf(fmaxf(fabsf((cy - 0.5f * (Bx.y + Bx.w)) * rbh), 1e-3f));
            float s, c;
            __sincosf(p0 * ivA, &s, &c);
            a[ci][0][0] = fmaxf(s, 0.0f); a[ci][1][0] = fmaxf(c, 0.0f);
            __sincosf(p0 * ivB, &s, &c);
            a[ci][0][1] = fmaxf(s, 0.0f); a[ci][1][1] = fmaxf(c, 0.0f);
            __sincosf(p1 * ivA, &s, &c);
            a[ci][2][0] = fmaxf(s, 0.0f); a[ci][3][0] = fmaxf(c, 0.0f);
            __sincosf(p1 * ivB, &s, &c);
            a[ci][2][1] = fmaxf(s, 0.0f); a[ci][3][1] = fmaxf(c, 0.0f);
            const float* tc = tabB + (size_t)col * 36;
            float2 cw0 = *(const float2*)(tc + 2 * tig);
            float2 cw1 = *(const float2*)(tc + 2 * tig + 8);
            float2 ch0 = *(const float2*)(tc + 16 + 2 * tig);
            float2 ch1 = *(const float2*)(tc + 24 + 2 * tig);
            a[ci][4][0] = fmaxf(cw0.x * rw0.y - cw0.y * rw0.x, 0.0f);
            a[ci][4][1] = fmaxf(cw1.x * rw1.y - cw1.y * rw1.x, 0.0f);
            a[ci][5][0] = fmaxf(cw0.y * rw0.y + cw0.x * rw0.x, 0.0f);
            a[ci][5][1] = fmaxf(cw1.y * rw1.y + cw1.x * rw1.x, 0.0f);
            a[ci][6][0] = fmaxf(ch0.x * rh0.y - ch0.y * rh0.x, 0.0f);
            a[ci][6][1] = fmaxf(ch1.x * rh1.y - ch1.y * rh1.x, 0.0f);
            a[ci][7][0] = fmaxf(ch0.y * rh0.y + ch0.x * rh0.x, 0.0f);
            a[ci][7][1] = fmaxf(ch1.y * rh1.y + ch1.x * rh1.x, 0.0f);
        }

        float acc[2][4];
#pragma unroll
        for (int j = 0; j < 2; j++)
#pragma unroll
            for (int q = 0; q < 4; q++) acc[j][q] = 0.0f;

#pragma unroll
        for (int kk = 0; kk < 8; kk++) {
            uint32_t ah[4], al[4];
#pragma unroll
            for (int q = 0; q < 4; q++) {
                float v = a[q & 1][kk][q >> 1];
                uint32_t h = f2tf(v);
                ah[q] = h;
                al[q] = f2tf(v - __uint_as_float(h));
            }
            int ko = 8 * kk + tig;
#pragma unroll
            for (int j = 0; j < 2; j++) {
                int rb = (8 * j + g4) * 68 + ko;
                uint32_t bh2[2], bl2[2];
                bh2[0] = __float_as_uint(wbh[rb]);
                bh2[1] = __float_as_uint(wbh[rb + 4]);
                bl2[0] = __float_as_uint(wbl[rb]);
                bl2[1] = __float_as_uint(wbl[rb + 4]);
                mma8(acc[j], ah, bh2);
                mma8(acc[j], ah, bl2);
                mma8(acc[j], al, bh2);
            }
        }

        int cA = base + g4, cB = cA + 8;
#pragma unroll
        for (int j = 0; j < 2; j++) {
            int ga = 8 * j + 2 * tig, gb = ga + 1;
            sl[ga * SLP + cA] = fmaxf(acc[j][0] + bp[ga], 1e-6f);
            sl[gb * SLP + cA] = fmaxf(acc[j][1] + bp[gb], 1e-6f);
            sl[ga * SLP + cB] = fmaxf(acc[j][2] + bp[ga], 1e-6f);
            sl[gb * SLP + cB] = fmaxf(acc[j][3] + bp[gb], 1e-6f);
        }
    }
    __syncthreads();

    // ---- phase 2: multiply by exp(scores) (coalesced) + sum-normalize ----
    int c0 = tid * 4;
    size_t sro = (size_t)r * NCOLS + c0;
    float sum[NG];
#pragma unroll
    for (int g = 0; g < NG; g++) {
        float4 v = *(float4*)&sl[g * SLP + c0];
        float4 e = *(const float4*)(Eb + (size_t)g * MN + sro);
        v.x *= e.x; v.y *= e.y; v.z *= e.z; v.w *= e.w;
        *(float4*)&sl[g * SLP + c0] = v;
        sum[g] = (v.x + v.y) + (v.z + v.w);
    }
#pragma unroll
    for (int g = 0; g < NG; g++) {
#pragma unroll
        for (int o = 16; o; o >>= 1)
            sum[g] += __shfl_xor_sync(0xffffffffu, sum[g], o);
    }
    if (lane == 0) {
#pragma unroll
        for (int g = 0; g < NG; g++) rbuf[g * (NW + 1) + wid] = sum[g];
    }
    __syncthreads();
    if (tid < NG) {
        float t = 0.0f;
#pragma unroll
        for (int w = 0; w < NW; w++) t += rbuf[tid * (NW + 1) + w];
        rbuf[tid * (NW + 1) + NW] = t;
    }
    __syncthreads();

#pragma unroll
    for (int g = 0; g < NG; g++) {
        float inv = __frcp_rn(rbuf[g * (NW + 1) + NW]);
        float4 v = *(float4*)&sl[g * SLP + c0];
        v.x = f2tff(v.x * inv); v.y = f2tff(v.y * inv);
        v.z = f2tff(v.z * inv); v.w = f2tff(v.w * inv);
        *(float4*)(L + (size_t)g * MN + (size_t)r * NCOLS + c0) = v;
    }
}

// ---------------------------------------------------------------------------
extern "C" void kernel_launch(void* const* d_in, const int* in_sizes, int n_in,
                              void* d_out, int out_size)
{
    (void)in_sizes; (void)n_in; (void)out_size;
    const float* feat      = (const float*)d_in[0];
    const float* ctx_feat  = (const float*)d_in[1];
    const float* box       = (const float*)d_in[2];
    const float* ctx_box   = (const float*)d_in[3];
    const float* w_fc_gt   = (const float*)d_in[4];
    const float* b_fc_gt   = (const float*)d_in[5];
    const float* w_fc_ctx  = (const float*)d_in[6];
    const float* b_fc_ctx  = (const float*)d_in[7];
    const float* w_pos_gt  = (const float*)d_in[8];
    const float* b_pos_gt  = (const float*)d_in[9];
    const float* w_pos_ctx = (const float*)d_in[10];
    const float* b_pos_ctx = (const float*)d_in[11];
    const float* w_conv    = (const float*)d_in[12];
    const float* b_conv    = (const float*)d_in[13];

    float* out = (float*)d_out;
    float* out_gt  = out;
    float* out_ctx = out + (size_t)M_GT * FEAT;

    float *E, *Et, *L1, *L2, *tabA, *tabB;
    cudaGetSymbolAddress((void**)&E,    g_E);
    cudaGetSymbolAddress((void**)&Et,   g_Et);
    cudaGetSymbolAddress((void**)&L1,   g_L1);
    cudaGetSymbolAddress((void**)&L2,   g_L2);
    cudaGetSymbolAddress((void**)&tabA, g_tabA);
    cudaGetSymbolAddress((void**)&tabB, g_tabB);

    static int attr_done = 0;
    if (!attr_done) {
        cudaFuncSetAttribute(proj_mma, cudaFuncAttributeMaxDynamicSharedMemorySize,
                             2 * PROJ_BUF * 4);
        cudaFuncSetAttribute(attn_mma, cudaFuncAttributeMaxDynamicSharedMemorySize,
                             2 * ATTN_BUF * 4);
        cudaFuncSetAttribute(pos_soft<N_CTX>, cudaFuncAttributeMaxDynamicSharedMemorySize,
                             NG * (N_CTX + 4) * 4);
        cudaFuncSetAttribute(pos_soft<M_GT>, cudaFuncAttributeMaxDynamicSharedMemorySize,
                             NG * (M_GT + 4) * 4);
        attr_done = 1;
    }

    // 0) per-box sin/cos tables
    boxtab_k<<<(M_GT + N_CTX + 127) / 128, 128>>>((const float4*)box,
                                                  (const float4*)ctx_box);
    // 1) Q, K, Ut, Vt projections (tf32-rounded outputs)
    proj_mma<<<dim3(8, 8, 4), 256, 2 * PROJ_BUF * 4>>>(
        feat, ctx_feat, w_fc_gt, b_fc_gt, w_fc_ctx, b_fc_ctx, w_conv);
    // 2) E = exp(scores), E + Et
    scores_mma<<<dim3(8, 4, 16), 256>>>();
    // 3) fused pos-embedding + exp-weight + normalize (tf32-rounded weights)
    pos_soft<N_CTX><<<M_GT, N_CTX / 4, NG * (N_CTX + 4) * 4>>>(
        (const float4*)box, (const float4*)ctx_box, tabA, tabB,
        w_pos_gt, b_pos_gt, E, L1);
    pos_soft<M_GT><<<N_CTX, M_GT / 4, NG * (M_GT + 4) * 4>>>(
        (const float4*)ctx_box, (const float4*)box, tabB, tabA,
        w_pos_ctx, b_pos_ctx, Et, L2);
    // 4) attention output (raw tf32 fragment loads)
    attn_mma<<<dim3(1, 8, 32), 256, 2 * ATTN_BUF * 4>>>(b_conv, out_gt, out_ctx);
}

// round 16
// speedup vs baseline: 1.0612x; 1.0109x over previous
#include <cuda_runtime.h>
#include <cstdint>

#define M_GT  512
#define N_CTX 1024
#define FEAT  1024
#define NG    16
#define DK    64
#define MN    (M_GT * N_CTX)   // 524288

// ---------------- device scratch (static globals; no allocation) ------------
// Q/K/Ut/Vt/L1/L2 hold tf32-rounded values (producers round; consumers load raw)
__device__ float g_Q [M_GT * FEAT];
__device__ float g_K [N_CTX * FEAT];
__device__ float g_Ut[FEAT * M_GT];    // Ut[o][m]
__device__ float g_Vt[FEAT * N_CTX];   // Vt[o][n]
__device__ float g_E [NG * MN];        // exp(scores)  (G, M, N)
__device__ float g_Et[NG * MN];        // exp(scores)^T (G, N, M)
__device__ float g_L1[NG * MN];        // UNNORMALIZED weights gt  (G, M, N)
__device__ float g_L2[NG * MN];        // UNNORMALIZED weights ctx (G, N, M)
__device__ float g_RS1[NG * M_GT];     // rowsums gt  [g][m]
__device__ float g_RS2[NG * N_CTX];    // rowsums ctx [g][n]
__device__ float g_tabA[M_GT * 36];    // per-box sin/cos tables (gt boxes)
__device__ float g_tabB[N_CTX * 36];   // per-box sin/cos tables (ctx boxes)

// 1000^(-j/8)
__constant__ float c_invdim[8] = {
    1.0f, 0.4216965034f, 0.1778279410f, 0.0749894209f,
    0.0316227766f, 0.0133352143f, 0.0056234133f, 0.0023713737f
};

// ======================= helpers ==========================
__device__ __forceinline__ uint32_t f2tf(float x) {
    uint32_t r;
    asm("cvt.rna.tf32.f32 %0, %1;" : "=r"(r) : "f"(x));
    return r;
}
__device__ __forceinline__ float f2tff(float x) {
    return __uint_as_float(f2tf(x));
}

__device__ __forceinline__ void mma8(float* c, const uint32_t* a, const uint32_t* b) {
    asm volatile(
        "mma.sync.aligned.m16n8k8.row.col.f32.tf32.tf32.f32 "
        "{%0,%1,%2,%3}, {%4,%5,%6,%7}, {%8,%9}, {%0,%1,%2,%3};"
        : "+f"(c[0]), "+f"(c[1]), "+f"(c[2]), "+f"(c[3])
        : "r"(a[0]), "r"(a[1]), "r"(a[2]), "r"(a[3]), "r"(b[0]), "r"(b[1]));
}

__device__ __forceinline__ void cp16(uint32_t s, const void* g) {
    asm volatile("cp.async.cg.shared.global [%0], [%1], 16;" :: "r"(s), "l"(g));
}
#define CP_COMMIT() asm volatile("cp.async.commit_group;" ::: "memory")
#define CP_WAIT1()  asm volatile("cp.async.wait_group 1;" ::: "memory")
#define CP_WAIT0()  asm volatile("cp.async.wait_group 0;" ::: "memory")

#define LDP 36   // smem row pitch (floats)

template <int ROWS>
__device__ __forceinline__ void issue_chunk(const float* __restrict__ g, int ld,
                                            uint32_t smbase, int tid)
{
#pragma unroll
    for (int i = 0; i < ROWS / 32; i++) {
        int idx = tid + i * 256;
        int r = idx >> 3, c = (idx & 7) << 2;
        cp16(smbase + (uint32_t)(r * LDP + c) * 4u, g + (size_t)r * ld + c);
    }
}

// raw staging (values already tf32-rounded by producer)
template <int ROWS>
__device__ __forceinline__ void stage_raw(const float* __restrict__ g, int ld,
                                          uint32_t* __restrict__ sm, int tid)
{
#pragma unroll
    for (int i = 0; i < ROWS / 32; i++) {
        int idx = tid + i * 256;
        int r = idx >> 3, c = (idx & 7) << 2;
        uint4 v = *(const uint4*)(g + (size_t)r * ld + c);
        *(uint4*)(sm + r * LDP + c) = v;
    }
}

// ---------------------------------------------------------------------------
// boxtab_k: per-box sin/cos tables for the separable dw/dh embedding dims.
// ---------------------------------------------------------------------------
__global__ void boxtab_k(const float4* __restrict__ box,
                         const float4* __restrict__ ctx_box)
{
    int i = blockIdx.x * 128 + threadIdx.x;
    float4 Bx; float* dst;
    if (i < M_GT) { Bx = box[i]; dst = g_tabA + (size_t)i * 36; }
    else if (i < M_GT + N_CTX) { Bx = ctx_box[i - M_GT]; dst = g_tabB + (size_t)(i - M_GT) * 36; }
    else return;
    float lw = 100.0f * __logf(Bx.z - Bx.x + 1.0f);
    float lh = 100.0f * __logf(Bx.w - Bx.y + 1.0f);
#pragma unroll
    for (int j = 0; j < 8; j++) {
        float s, c;
        __sincosf(lw * c_invdim[j], &s, &c);
        dst[2 * j] = s; dst[2 * j + 1] = c;
        __sincosf(lh * c_invdim[j], &s, &c);
        dst[16 + 2 * j] = s; dst[17 + 2 * j] = c;
    }
}

// ---------------------------------------------------------------------------
// proj_mma: C = tf32_round(A @ W^T (+bias)). 128x128 tiles, K=1024.
// ---------------------------------------------------------------------------
#define PROJ_BUF (128 * LDP * 2)

__global__ __launch_bounds__(256, 2) void proj_mma(
    const float* __restrict__ feat, const float* __restrict__ ctx_feat,
    const float* __restrict__ w_gt, const float* __restrict__ b_gt,
    const float* __restrict__ w_ctx, const float* __restrict__ b_ctx,
    const float* __restrict__ w_conv)
{
    const float* A; const float* W; const float* bias; float* C;
    int Mrows, Ncols;
    switch (blockIdx.z) {
    case 0:  A = feat;   W = w_gt;     bias = b_gt;  C = g_Q;  Mrows = M_GT;  Ncols = FEAT;  break;
    case 1:  A = ctx_feat; W = w_ctx;  bias = b_ctx; C = g_K;  Mrows = N_CTX; Ncols = FEAT;  break;
    case 2:  A = w_conv; W = feat;     bias = 0;     C = g_Ut; Mrows = FEAT;  Ncols = M_GT;  break;
    default: A = w_conv; W = ctx_feat; bias = 0;     C = g_Vt; Mrows = FEAT;  Ncols = N_CTX; break;
    }
    int bm = blockIdx.y * 128, bn = blockIdx.x * 128;
    if (bm >= Mrows || bn >= Ncols) return;

    extern __shared__ float dsm[];
    uint32_t smb = (uint32_t)__cvta_generic_to_shared(dsm);

    int tid = threadIdx.x, wid = tid >> 5, lane = tid & 31;
    int g4 = lane >> 2, tig = lane & 3;
    int wm = (wid & 1) * 64, wn = (wid >> 1) * 32;

    float acc[4][4][4];
#pragma unroll
    for (int i = 0; i < 4; i++)
#pragma unroll
        for (int j = 0; j < 4; j++)
#pragma unroll
            for (int q = 0; q < 4; q++) acc[i][j][q] = 0.0f;

    const float* Ab = A + (size_t)bm * FEAT;
    const float* Wb = W + (size_t)bn * FEAT;

    issue_chunk<128>(Ab, FEAT, smb, tid);
    issue_chunk<128>(Wb, FEAT, smb + 128 * LDP * 4u, tid);
    CP_COMMIT();

    const int NCH = FEAT / 32;
    for (int ch = 0; ch < NCH; ch++) {
        int buf = ch & 1;
        if (ch + 1 < NCH) {
            uint32_t nb = smb + (uint32_t)((ch + 1) & 1) * PROJ_BUF * 4u;
            issue_chunk<128>(Ab + (ch + 1) * 32, FEAT, nb, tid);
            issue_chunk<128>(Wb + (ch + 1) * 32, FEAT, nb + 128 * LDP * 4u, tid);
            CP_COMMIT();
            CP_WAIT1();
        } else {
            CP_WAIT0();
        }
        __syncthreads();
        const float* As = dsm + buf * PROJ_BUF;
        const float* Bs = As + 128 * LDP;
#pragma unroll
        for (int kk = 0; kk < 4; kk++) {
            int k0 = kk * 8 + tig;
            uint32_t bf[4][2];
#pragma unroll
            for (int j = 0; j < 4; j++) {
                int rn = (wn + j * 8 + g4) * LDP;
                bf[j][0] = f2tf(Bs[rn + k0]);
                bf[j][1] = f2tf(Bs[rn + k0 + 4]);
            }
#pragma unroll
            for (int i = 0; i < 4; i++) {
                int r0 = (wm + i * 16 + g4) * LDP;
                uint32_t af[4];
                af[0] = f2tf(As[r0 + k0]);
                af[1] = f2tf(As[r0 + 8 * LDP + k0]);
                af[2] = f2tf(As[r0 + k0 + 4]);
                af[3] = f2tf(As[r0 + 8 * LDP + k0 + 4]);
#pragma unroll
                for (int j = 0; j < 4; j++) mma8(acc[i][j], af, bf[j]);
            }
        }
        __syncthreads();
    }

#pragma unroll
    for (int i = 0; i < 4; i++) {
        int row = bm + wm + i * 16 + g4;
#pragma unroll
        for (int j = 0; j < 4; j++) {
            int col = bn + wn + j * 8 + 2 * tig;
            float b0 = bias ? bias[col] : 0.0f;
            float b1 = bias ? bias[col + 1] : 0.0f;
            float2 o0, o1;
            o0.x = f2tff(acc[i][j][0] + b0); o0.y = f2tff(acc[i][j][1] + b1);
            o1.x = f2tff(acc[i][j][2] + b0); o1.y = f2tff(acc[i][j][3] + b1);
            *(float2*)(C + (size_t)row * Ncols + col)       = o0;
            *(float2*)(C + (size_t)(row + 8) * Ncols + col) = o1;
        }
    }
}

// ---------------------------------------------------------------------------
// scores_mma: E[g,m,n] = exp(0.125 * Q.K) ; Et[g,n,m] via smem transpose.
// ---------------------------------------------------------------------------
#define TP 68

__global__ __launch_bounds__(256, 2) void scores_mma()
{
    int g = blockIdx.z;
    int bm = blockIdx.y * 128, bn = blockIdx.x * 128;
    const float* A = g_Q + (size_t)bm * FEAT + g * DK;
    const float* B = g_K + (size_t)bn * FEAT + g * DK;
    float* C  = g_E  + (size_t)g * MN;
    float* Ct = g_Et + (size_t)g * MN;

    __shared__ __align__(16) uint32_t sbuf[2 * 128 * LDP];
    uint32_t* As = sbuf;
    uint32_t* Bs = sbuf + 128 * LDP;
    float* T = (float*)sbuf;

    int tid = threadIdx.x, wid = tid >> 5, lane = tid & 31;
    int g4 = lane >> 2, tig = lane & 3;
    int wm = (wid & 1) * 64, wn = (wid >> 1) * 32;

    float acc[4][4][4];
#pragma unroll
    for (int i = 0; i < 4; i++)
#pragma unroll
        for (int j = 0; j < 4; j++)
#pragma unroll
            for (int q = 0; q < 4; q++) acc[i][j][q] = 0.0f;

    for (int ch = 0; ch < 2; ch++) {
        stage_raw<128>(A + ch * 32, FEAT, As, tid);
        stage_raw<128>(B + ch * 32, FEAT, Bs, tid);
        __syncthreads();
#pragma unroll
        for (int kk = 0; kk < 4; kk++) {
            int k0 = kk * 8 + tig;
            uint32_t bf[4][2];
#pragma unroll
            for (int j = 0; j < 4; j++) {
                int rn = (wn + j * 8 + g4) * LDP;
                bf[j][0] = Bs[rn + k0];
                bf[j][1] = Bs[rn + k0 + 4];
            }
#pragma unroll
            for (int i = 0; i < 4; i++) {
                int r0 = (wm + i * 16 + g4) * LDP;
                uint32_t af[4];
                af[0] = As[r0 + k0];
                af[1] = As[r0 + 8 * LDP + k0];
                af[2] = As[r0 + k0 + 4];
                af[3] = As[r0 + 8 * LDP + k0 + 4];
#pragma unroll
                for (int j = 0; j < 4; j++) mma8(acc[i][j], af, bf[j]);
            }
        }
        __syncthreads();
    }

#pragma unroll
    for (int i = 0; i < 4; i++)
#pragma unroll
        for (int j = 0; j < 4; j++)
#pragma unroll
            for (int q = 0; q < 4; q++)
                acc[i][j][q] = __expf(acc[i][j][q] * 0.125f);

#pragma unroll
    for (int i = 0; i < 4; i++) {
        int row = bm + wm + i * 16 + g4;
#pragma unroll
        for (int j = 0; j < 4; j++) {
            int col = bn + wn + j * 8 + 2 * tig;
            float2 o0, o1;
            o0.x = acc[i][j][0]; o0.y = acc[i][j][1];
            o1.x = acc[i][j][2]; o1.y = acc[i][j][3];
            *(float2*)(C + (size_t)row * N_CTX + col)       = o0;
            *(float2*)(C + (size_t)(row + 8) * N_CTX + col) = o1;
        }
    }

    for (int hh = 0; hh < 2; hh++) {
        __syncthreads();
        if ((wid & 1) == hh) {
#pragma unroll
            for (int i = 0; i < 4; i++) {
                int rl = i * 16 + g4;
#pragma unroll
                for (int j = 0; j < 4; j++) {
                    int col = wn + j * 8 + 2 * tig;
                    T[col * TP + rl]            = acc[i][j][0];
                    T[(col + 1) * TP + rl]      = acc[i][j][1];
                    T[col * TP + rl + 8]        = acc[i][j][2];
                    T[(col + 1) * TP + rl + 8]  = acc[i][j][3];
                }
            }
        }
        __syncthreads();
        int col = tid >> 1, seg = (tid & 1) << 5;
        const float* src = T + col * TP + seg;
        float* dst = Ct + (size_t)(bn + col) * M_GT + bm + hh * 64 + seg;
#pragma unroll
        for (int k = 0; k < 8; k++)
            *(float4*)(dst + k * 4) = *(const float4*)(src + k * 4);
    }
}

// ---------------------------------------------------------------------------
// attn_mma: z 0..15 gt, z 16..31 ctx. 128x64 tiles, warp tile 64x16.
// Deferred softmax normalization: epilogue scales by 1/rowsum.
// ---------------------------------------------------------------------------
#define ATTN_BUF (128 * LDP + 64 * LDP)

__global__ __launch_bounds__(256, 2) void attn_mma(
    const float* __restrict__ b_conv, float* __restrict__ out_gt,
    float* __restrict__ out_ctx)
{
    int z = blockIdx.z;
    int g = z & 15;
    bool gt = z < 16;
    const float* A = gt ? g_L1 + (size_t)g * MN : g_L2 + (size_t)g * MN;
    const float* B = gt ? g_Vt + (size_t)(g * DK) * N_CTX
                        : g_Ut + (size_t)(g * DK) * M_GT;
    const float* RS = gt ? g_RS1 : g_RS2;
    float* C  = gt ? out_gt : out_ctx;
    int Mrows = gt ? M_GT : N_CTX;
    int Ktot  = gt ? N_CTX : M_GT;
    int bm = blockIdx.y * 128;
    if (bm >= Mrows) return;

    extern __shared__ float dsm[];
    uint32_t smb = (uint32_t)__cvta_generic_to_shared(dsm);
    __shared__ float rs_s[128];

    int tid = threadIdx.x, wid = tid >> 5, lane = tid & 31;
    int g4 = lane >> 2, tig = lane & 3;
    int wm = (wid & 1) * 64, wn = (wid >> 1) * 16;

    if (tid < 128) rs_s[tid] = RS[(size_t)g * Mrows + bm + tid];

    float acc[4][2][4];
#pragma unroll
    for (int i = 0; i < 4; i++)
#pragma unroll
        for (int j = 0; j < 2; j++)
#pragma unroll
            for (int q = 0; q < 4; q++) acc[i][j][q] = 0.0f;

    const float* Ab = A + (size_t)bm * Ktot;

    issue_chunk<128>(Ab, Ktot, smb, tid);
    issue_chunk<64>(B, Ktot, smb + 128 * LDP * 4u, tid);
    CP_COMMIT();

    int NCH = Ktot / 32;
    for (int ch = 0; ch < NCH; ch++) {
        int buf = ch & 1;
        if (ch + 1 < NCH) {
            uint32_t nb = smb + (uint32_t)((ch + 1) & 1) * ATTN_BUF * 4u;
            issue_chunk<128>(Ab + (ch + 1) * 32, Ktot, nb, tid);
            issue_chunk<64>(B + (ch + 1) * 32, Ktot, nb + 128 * LDP * 4u, tid);
            CP_COMMIT();
            CP_WAIT1();
        } else {
            CP_WAIT0();
        }
        __syncthreads();
        const uint32_t* As = (const uint32_t*)(dsm + buf * ATTN_BUF);
        const uint32_t* Bs = As + 128 * LDP;
#pragma unroll
        for (int kk = 0; kk < 4; kk++) {
            int k0 = kk * 8 + tig;
            uint32_t bf[2][2];
#pragma unroll
            for (int j = 0; j < 2; j++) {
                int rn = (wn + j * 8 + g4) * LDP;
                bf[j][0] = Bs[rn + k0];
                bf[j][1] = Bs[rn + k0 + 4];
            }
#pragma unroll
            for (int i = 0; i < 4; i++) {
                int r0 = (wm + i * 16 + g4) * LDP;
                uint32_t af[4];
                af[0] = As[r0 + k0];
                af[1] = As[r0 + 8 * LDP + k0];
                af[2] = As[r0 + k0 + 4];
                af[3] = As[r0 + 8 * LDP + k0 + 4];
#pragma unroll
                for (int j = 0; j < 2; j++) mma8(acc[i][j], af, bf[j]);
            }
        }
        __syncthreads();
    }

#pragma unroll
    for (int i = 0; i < 4; i++) {
        int rl = wm + i * 16 + g4;
        int row = bm + rl;
        float rinv0 = __frcp_rn(rs_s[rl]);
        float rinv1 = __frcp_rn(rs_s[rl + 8]);
#pragma unroll
        for (int j = 0; j < 2; j++) {
            int col = g * DK + wn + j * 8 + 2 * tig;
            float b0 = b_conv[col], b1 = b_conv[col + 1];
            float2 o0, o1;
            o0.x = acc[i][j][0] * rinv0 + b0; o0.y = acc[i][j][1] * rinv0 + b1;
            o1.x = acc[i][j][2] * rinv1 + b0; o1.y = acc[i][j][3] * rinv1 + b1;
            *(float2*)(C + (size_t)row * FEAT + col)       = o0;
            *(float2*)(C + (size_t)(row + 8) * FEAT + col) = o1;
        }
    }
}

// ---------------------------------------------------------------------------
// pos_soft<NCOLS>: fused pos-embedding + exp-weight product. Writes
// UNNORMALIZED weights w~ = tf32(max(pos+b,1e-6)*E) and rowsums RS[g][r].
// Normalization deferred to attn epilogue.
// ---------------------------------------------------------------------------
template <int NCOLS>
__global__ __launch_bounds__(NCOLS / 4, 512 / (NCOLS / 4)) void pos_soft(
    const float4* __restrict__ boxA, const float4* __restrict__ boxB,
    const float* __restrict__ tabA, const float* __restrict__ tabB,
    const float* __restrict__ w_pos, const float* __restrict__ b_pos,
    const float* __restrict__ Eb, float* __restrict__ L, float* __restrict__ RS)
{
    constexpr int NT = NCOLS / 4;
    constexpr int NW = NT / 32;
    constexpr int SLP = NCOLS + 4;            // smem pitch
    extern __shared__ float sl[];             // [NG][SLP]
    __shared__ float wbh[16 * 68];            // w_pos tf32-hi, pitch 68
    __shared__ float wbl[16 * 68];            // w_pos tf32-lo
    __shared__ float bp[NG];
    __shared__ float rbuf[NG * NW];

    int tid = threadIdx.x, wid = tid >> 5, lane = tid & 31;
    int g4 = lane >> 2, tig = lane & 3;

    for (int i = tid; i < 1024; i += NT) {
        int g = i >> 6, f = i & 63;
        float w = w_pos[i];
        uint32_t hb = f2tf(w);
        float hf = __uint_as_float(hb);
        wbh[g * 68 + f] = hf;
        wbl[g * 68 + f] = __uint_as_float(f2tf(w - hf));
    }
    if (tid < NG) bp[tid] = b_pos[tid];
    __syncthreads();

    int r = blockIdx.x;
    float4 A = boxA[r];
    float bw = A.z - A.x + 1.0f, bh = A.w - A.y + 1.0f;
    float cx = 0.5f * (A.x + A.z), cy = 0.5f * (A.y + A.w);
    float rbw = 1.0f / bw, rbh = 1.0f / bh;
    float ivA = c_invdim[tig], ivB = c_invdim[tig + 4];

    const float* tr = tabA + (size_t)r * 36;
    float2 rw0 = *(const float2*)(tr + 2 * tig);
    float2 rw1 = *(const float2*)(tr + 2 * tig + 8);
    float2 rh0 = *(const float2*)(tr + 16 + 2 * tig);
    float2 rh1 = *(const float2*)(tr + 24 + 2 * tig);

    for (int mt = 0; mt < 8; mt++) {
        int base = wid * 128 + mt * 16;
        float a[2][8][2];   // [col ci][kk][k-half]
#pragma unroll
        for (int ci = 0; ci < 2; ci++) {
            int col = base + ci * 8 + g4;
            float4 Bx = boxB[col];
            float p0 = 100.0f * __logf(fmaxf(fabsf((cx - 0.5f * (Bx.x + Bx.z)) * rbw), 1e-3f));
            float p1 = 100.0f * __logf(fmaxf(fabsf((cy - 0.5f * (Bx.y + Bx.w)) * rbh), 1e-3f));
            float s, c;
            __sincosf(p0 * ivA, &s, &c);
            a[ci][0][0] = fmaxf(s, 0.0f); a[ci][1][0] = fmaxf(c, 0.0f);
            __sincosf(p0 * ivB, &s, &c);
            a[ci][0][1] = fmaxf(s, 0.0f); a[ci][1][1] = fmaxf(c, 0.0f);
            __sincosf(p1 * ivA, &s, &c);
            a[ci][2][0] = fmaxf(s, 0.0f); a[ci][3][0] = fmaxf(c, 0.0f);
            __sincosf(p1 * ivB, &s, &c);
            a[ci][2][1] = fmaxf(s, 0.0f); a[ci][3][1] = fmaxf(c, 0.0f);
            const float* tc = tabB + (size_t)col * 36;
            float2 cw0 = *(const float2*)(tc + 2 * tig);
            float2 cw1 = *(const float2*)(tc + 2 * tig + 8);
            float2 ch0 = *(const float2*)(tc + 16 + 2 * tig);
            float2 ch1 = *(const float2*)(tc + 24 + 2 * tig);
            a[ci][4][0] = fmaxf(cw0.x * rw0.y - cw0.y * rw0.x, 0.0f);
            a[ci][4][1] = fmaxf(cw1.x * rw1.y - cw1.y * rw1.x, 0.0f);
            a[ci][5][0] = fmaxf(cw0.y * rw0.y + cw0.x * rw0.x, 0.0f);
            a[ci][5][1] = fmaxf(cw1.y * rw1.y + cw1.x * rw1.x, 0.0f);
            a[ci][6][0] = fmaxf(ch0.x * rh0.y - ch0.y * rh0.x, 0.0f);
            a[ci][6][1] = fmaxf(ch1.x * rh1.y - ch1.y * rh1.x, 0.0f);
            a[ci][7][0] = fmaxf(ch0.y * rh0.y + ch0.x * rh0.x, 0.0f);
            a[ci][7][1] = fmaxf(ch1.y * rh1.y + ch1.x * rh1.x, 0.0f);
        }

        float acc[2][4];
#pragma unroll
        for (int j = 0; j < 2; j++)
#pragma unroll
            for (int q = 0; q < 4; q++) acc[j][q] = 0.0f;

#pragma unroll
        for (int kk = 0; kk < 8; kk++) {
            uint32_t ah[4], al[4];
#pragma unroll
            for (int q = 0; q < 4; q++) {
                float v = a[q & 1][kk][q >> 1];
                uint32_t h = f2tf(v);
                ah[q] = h;
                al[q] = f2tf(v - __uint_as_float(h));
            }
            int ko = 8 * kk + tig;
#pragma unroll
            for (int j = 0; j < 2; j++) {
                int rb = (8 * j + g4) * 68 + ko;
                uint32_t bh2[2], bl2[2];
                bh2[0] = __float_as_uint(wbh[rb]);
                bh2[1] = __float_as_uint(wbh[rb + 4]);
                bl2[0] = __float_as_uint(wbl[rb]);
                bl2[1] = __float_as_uint(wbl[rb + 4]);
                mma8(acc[j], ah, bh2);
                mma8(acc[j], ah, bl2);
                mma8(acc[j], al, bh2);
            }
        }

        int cA = base + g4, cB = cA + 8;
#pragma unroll
        for (int j = 0; j < 2; j++) {
            int ga = 8 * j + 2 * tig, gb = ga + 1;
            sl[ga * SLP + cA] = fmaxf(acc[j][0] + bp[ga], 1e-6f);
            sl[gb * SLP + cA] = fmaxf(acc[j][1] + bp[gb], 1e-6f);
            sl[ga * SLP + cB] = fmaxf(acc[j][2] + bp[ga], 1e-6f);
            sl[gb * SLP + cB] = fmaxf(acc[j][3] + bp[gb], 1e-6f);
        }
    }
    __syncthreads();

    // ---- phase 2: single pass: w~ = tf32(pos * E) -> L, accumulate rowsum --
    int c0 = tid * 4;
    size_t sro = (size_t)r * NCOLS + c0;
    float sum[NG];
#pragma unroll
    for (int g = 0; g < NG; g++) {
        float4 v = *(float4*)&sl[g * SLP + c0];
        float4 e = *(const float4*)(Eb + (size_t)g * MN + sro);
        v.x = f2tff(v.x * e.x); v.y = f2tff(v.y * e.y);
        v.z = f2tff(v.z * e.z); v.w = f2tff(v.w * e.w);
        *(float4*)(L + (size_t)g * MN + sro) = v;
        sum[g] = (v.x + v.y) + (v.z + v.w);
    }
#pragma unroll
    for (int g = 0; g < NG; g++) {
#pragma unroll
        for (int o = 16; o; o >>= 1)
            sum[g] += __shfl_xor_sync(0xffffffffu, sum[g], o);
    }
    if (lane == 0) {
#pragma unroll
        for (int g = 0; g < NG; g++) rbuf[g * NW + wid] = sum[g];
    }
    __syncthreads();
    if (tid < NG) {
        float t = 0.0f;
#pragma unroll
        for (int w = 0; w < NW; w++) t += rbuf[tid * NW + w];
        RS[(size_t)tid * gridDim.x + r] = t;
    }
}

// ---------------------------------------------------------------------------
extern "C" void kernel_launch(void* const* d_in, const int* in_sizes, int n_in,
                              void* d_out, int out_size)
{
    (void)in_sizes; (void)n_in; (void)out_size;
    const float* feat      = (const float*)d_in[0];
    const float* ctx_feat  = (const float*)d_in[1];
    const float* box       = (const float*)d_in[2];
    const float* ctx_box   = (const float*)d_in[3];
    const float* w_fc_gt   = (const float*)d_in[4];
    const float* b_fc_gt   = (const float*)d_in[5];
    const float* w_fc_ctx  = (const float*)d_in[6];
    const float* b_fc_ctx  = (const float*)d_in[7];
    const float* w_pos_gt  = (const float*)d_in[8];
    const float* b_pos_gt  = (const float*)d_in[9];
    const float* w_pos_ctx = (const float*)d_in[10];
    const float* b_pos_ctx = (const float*)d_in[11];
    const float* w_conv    = (const float*)d_in[12];
    const float* b_conv    = (const float*)d_in[13];

    float* out = (float*)d_out;
    float* out_gt  = out;
    float* out_ctx = out + (size_t)M_GT * FEAT;

    float *E, *Et, *L1, *L2, *RS1, *RS2, *tabA, *tabB;
    cudaGetSymbolAddress((void**)&E,    g_E);
    cudaGetSymbolAddress((void**)&Et,   g_Et);
    cudaGetSymbolAddress((void**)&L1,   g_L1);
    cudaGetSymbolAddress((void**)&L2,   g_L2);
    cudaGetSymbolAddress((void**)&RS1,  g_RS1);
    cudaGetSymbolAddress((void**)&RS2,  g_RS2);
    cudaGetSymbolAddress((void**)&tabA, g_tabA);
    cudaGetSymbolAddress((void**)&tabB, g_tabB);

    static int attr_done = 0;
    if (!attr_done) {
        cudaFuncSetAttribute(proj_mma, cudaFuncAttributeMaxDynamicSharedMemorySize,
                             2 * PROJ_BUF * 4);
        cudaFuncSetAttribute(attn_mma, cudaFuncAttributeMaxDynamicSharedMemorySize,
                             2 * ATTN_BUF * 4);
        cudaFuncSetAttribute(pos_soft<N_CTX>, cudaFuncAttributeMaxDynamicSharedMemorySize,
                             NG * (N_CTX + 4) * 4);
        cudaFuncSetAttribute(pos_soft<M_GT>, cudaFuncAttributeMaxDynamicSharedMemorySize,
                             NG * (M_GT + 4) * 4);
        attr_done = 1;
    }

    // 0) per-box sin/cos tables
    boxtab_k<<<(M_GT + N_CTX + 127) / 128, 128>>>((const float4*)box,
                                                  (const float4*)ctx_box);
    // 1) Q, K, Ut, Vt projections (tf32-rounded outputs)
    proj_mma<<<dim3(8, 8, 4), 256, 2 * PROJ_BUF * 4>>>(
        feat, ctx_feat, w_fc_gt, b_fc_gt, w_fc_ctx, b_fc_ctx, w_conv);
    // 2) E = exp(scores), E + Et
    scores_mma<<<dim3(8, 4, 16), 256>>>();
    // 3) fused pos-embedding + exp-weight (unnormalized) + rowsums
    pos_soft<N_CTX><<<M_GT, N_CTX / 4, NG * (N_CTX + 4) * 4>>>(
        (const float4*)box, (const float4*)ctx_box, tabA, tabB,
        w_pos_gt, b_pos_gt, E, L1, RS1);
    pos_soft<M_GT><<<N_CTX, M_GT / 4, NG * (M_GT + 4) * 4>>>(
        (const float4*)ctx_box, (const float4*)box, tabB, tabA,
        w_pos_ctx, b_pos_ctx, Et, L2, RS2);
    // 4) attention output (deferred normalization in epilogue)
    attn_mma<<<dim3(1, 8, 32), 256, 2 * ATTN_BUF * 4>>>(b_conv, out_gt, out_ctx);
}

// round 17
// speedup vs baseline: 1.0893x; 1.0265x over previous
#include <cuda_runtime.h>
#include <cstdint>

#define M_GT  512
#define N_CTX 1024
#define FEAT  1024
#define NG    16
#define DK    64
#define MN    (M_GT * N_CTX)   // 524288

// ---------------- device scratch (static globals; no allocation) ------------
__device__ float g_Q [M_GT * FEAT];
__device__ float g_K [N_CTX * FEAT];
__device__ float g_Ut[FEAT * M_GT];    // Ut[o][m]
__device__ float g_Vt[FEAT * N_CTX];   // Vt[o][n]
__device__ float g_E [NG * MN];        // exp(scores)  (G, M, N)
__device__ float g_Et[NG * MN];        // exp(scores)^T (G, N, M)
__device__ float g_L1[NG * MN];        // UNNORMALIZED weights gt  (G, M, N)
__device__ float g_L2[NG * MN];        // UNNORMALIZED weights ctx (G, N, M)
__device__ float g_RS1[NG * M_GT];     // rowsums gt  [g][m]
__device__ float g_RS2[NG * N_CTX];    // rowsums ctx [g][n]
__device__ float g_tabA[M_GT * 36];    // per-box sin/cos tables (gt boxes)
__device__ float g_tabB[N_CTX * 36];   // per-box sin/cos tables (ctx boxes)

// 1000^(-j/8)
__constant__ float c_invdim[8] = {
    1.0f, 0.4216965034f, 0.1778279410f, 0.0749894209f,
    0.0316227766f, 0.0133352143f, 0.0056234133f, 0.0023713737f
};

// ======================= helpers ==========================
__device__ __forceinline__ uint32_t f2tf(float x) {
    uint32_t r;
    asm("cvt.rna.tf32.f32 %0, %1;" : "=r"(r) : "f"(x));
    return r;
}
__device__ __forceinline__ float f2tff(float x) {
    return __uint_as_float(f2tf(x));
}

__device__ __forceinline__ void mma8(float* c, const uint32_t* a, const uint32_t* b) {
    asm volatile(
        "mma.sync.aligned.m16n8k8.row.col.f32.tf32.tf32.f32 "
        "{%0,%1,%2,%3}, {%4,%5,%6,%7}, {%8,%9}, {%0,%1,%2,%3};"
        : "+f"(c[0]), "+f"(c[1]), "+f"(c[2]), "+f"(c[3])
        : "r"(a[0]), "r"(a[1]), "r"(a[2]), "r"(a[3]), "r"(b[0]), "r"(b[1]));
}

__device__ __forceinline__ void cp16(uint32_t s, const void* g) {
    asm volatile("cp.async.cg.shared.global [%0], [%1], 16;" :: "r"(s), "l"(g));
}
#define CP_COMMIT() asm volatile("cp.async.commit_group;" ::: "memory")
#define CP_WAIT1()  asm volatile("cp.async.wait_group 1;" ::: "memory")
#define CP_WAIT0()  asm volatile("cp.async.wait_group 0;" ::: "memory")

#define LDP 36   // smem row pitch (floats)

template <int ROWS>
__device__ __forceinline__ void issue_chunk(const float* __restrict__ g, int ld,
                                            uint32_t smbase, int tid)
{
#pragma unroll
    for (int i = 0; i < ROWS / 32; i++) {
        int idx = tid + i * 256;
        int r = idx >> 3, c = (idx & 7) << 2;
        cp16(smbase + (uint32_t)(r * LDP + c) * 4u, g + (size_t)r * ld + c);
    }
}

// ---------------------------------------------------------------------------
// box table computation (device helper, called from proj_mma z=4 slice)
// ---------------------------------------------------------------------------
__device__ __forceinline__ void boxtab_compute(const float4* __restrict__ box,
                                               const float4* __restrict__ ctx_box,
                                               int i)
{
    float4 Bx; float* dst;
    if (i < M_GT) { Bx = box[i]; dst = g_tabA + (size_t)i * 36; }
    else if (i < M_GT + N_CTX) { Bx = ctx_box[i - M_GT]; dst = g_tabB + (size_t)(i - M_GT) * 36; }
    else return;
    float lw = 100.0f * __logf(Bx.z - Bx.x + 1.0f);
    float lh = 100.0f * __logf(Bx.w - Bx.y + 1.0f);
#pragma unroll
    for (int j = 0; j < 8; j++) {
        float s, c;
        __sincosf(lw * c_invdim[j], &s, &c);
        dst[2 * j] = s; dst[2 * j + 1] = c;
        __sincosf(lh * c_invdim[j], &s, &c);
        dst[16 + 2 * j] = s; dst[17 + 2 * j] = c;
    }
}

// ---------------------------------------------------------------------------
// proj_mma: C = tf32_round(A @ W^T (+bias)). 128x128 tiles, K=1024.
// z=4 slice computes the box sin/cos tables (folded launch).
// ---------------------------------------------------------------------------
#define PROJ_BUF (128 * LDP * 2)

__global__ __launch_bounds__(256, 2) void proj_mma(
    const float* __restrict__ feat, const float* __restrict__ ctx_feat,
    const float* __restrict__ w_gt, const float* __restrict__ b_gt,
    const float* __restrict__ w_ctx, const float* __restrict__ b_ctx,
    const float* __restrict__ w_conv,
    const float4* __restrict__ box, const float4* __restrict__ ctx_box)
{
    if (blockIdx.z == 4) {
        if (blockIdx.y == 0 && blockIdx.x < 6)
            boxtab_compute(box, ctx_box, blockIdx.x * 256 + threadIdx.x);
        return;
    }

    const float* A; const float* W; const float* bias; float* C;
    int Mrows, Ncols;
    switch (blockIdx.z) {
    case 0:  A = feat;   W = w_gt;     bias = b_gt;  C = g_Q;  Mrows = M_GT;  Ncols = FEAT;  break;
    case 1:  A = ctx_feat; W = w_ctx;  bias = b_ctx; C = g_K;  Mrows = N_CTX; Ncols = FEAT;  break;
    case 2:  A = w_conv; W = feat;     bias = 0;     C = g_Ut; Mrows = FEAT;  Ncols = M_GT;  break;
    default: A = w_conv; W = ctx_feat; bias = 0;     C = g_Vt; Mrows = FEAT;  Ncols = N_CTX; break;
    }
    int bm = blockIdx.y * 128, bn = blockIdx.x * 128;
    if (bm >= Mrows || bn >= Ncols) return;

    extern __shared__ float dsm[];
    uint32_t smb = (uint32_t)__cvta_generic_to_shared(dsm);

    int tid = threadIdx.x, wid = tid >> 5, lane = tid & 31;
    int g4 = lane >> 2, tig = lane & 3;
    int wm = (wid & 1) * 64, wn = (wid >> 1) * 32;

    float acc[4][4][4];
#pragma unroll
    for (int i = 0; i < 4; i++)
#pragma unroll
        for (int j = 0; j < 4; j++)
#pragma unroll
            for (int q = 0; q < 4; q++) acc[i][j][q] = 0.0f;

    const float* Ab = A + (size_t)bm * FEAT;
    const float* Wb = W + (size_t)bn * FEAT;

    issue_chunk<128>(Ab, FEAT, smb, tid);
    issue_chunk<128>(Wb, FEAT, smb + 128 * LDP * 4u, tid);
    CP_COMMIT();

    const int NCH = FEAT / 32;
    for (int ch = 0; ch < NCH; ch++) {
        int buf = ch & 1;
        if (ch + 1 < NCH) {
            uint32_t nb = smb + (uint32_t)((ch + 1) & 1) * PROJ_BUF * 4u;
            issue_chunk<128>(Ab + (ch + 1) * 32, FEAT, nb, tid);
            issue_chunk<128>(Wb + (ch + 1) * 32, FEAT, nb + 128 * LDP * 4u, tid);
            CP_COMMIT();
            CP_WAIT1();
        } else {
            CP_WAIT0();
        }
        __syncthreads();
        const float* As = dsm + buf * PROJ_BUF;
        const float* Bs = As + 128 * LDP;
#pragma unroll
        for (int kk = 0; kk < 4; kk++) {
            int k0 = kk * 8 + tig;
            uint32_t bf[4][2];
#pragma unroll
            for (int j = 0; j < 4; j++) {
                int rn = (wn + j * 8 + g4) * LDP;
                bf[j][0] = f2tf(Bs[rn + k0]);
                bf[j][1] = f2tf(Bs[rn + k0 + 4]);
            }
#pragma unroll
            for (int i = 0; i < 4; i++) {
                int r0 = (wm + i * 16 + g4) * LDP;
                uint32_t af[4];
                af[0] = f2tf(As[r0 + k0]);
                af[1] = f2tf(As[r0 + 8 * LDP + k0]);
                af[2] = f2tf(As[r0 + k0 + 4]);
                af[3] = f2tf(As[r0 + 8 * LDP + k0 + 4]);
#pragma unroll
                for (int j = 0; j < 4; j++) mma8(acc[i][j], af, bf[j]);
            }
        }
        __syncthreads();
    }

#pragma unroll
    for (int i = 0; i < 4; i++) {
        int row = bm + wm + i * 16 + g4;
#pragma unroll
        for (int j = 0; j < 4; j++) {
            int col = bn + wn + j * 8 + 2 * tig;
            float b0 = bias ? bias[col] : 0.0f;
            float b1 = bias ? bias[col + 1] : 0.0f;
            float2 o0, o1;
            o0.x = f2tff(acc[i][j][0] + b0); o0.y = f2tff(acc[i][j][1] + b1);
            o1.x = f2tff(acc[i][j][2] + b0); o1.y = f2tff(acc[i][j][3] + b1);
            *(float2*)(C + (size_t)row * Ncols + col)       = o0;
            *(float2*)(C + (size_t)(row + 8) * Ncols + col) = o1;
        }
    }
}

// ---------------------------------------------------------------------------
// scores_mma: E[g,m,n] = exp(0.125 * Q.K) ; Et[g,n,m] via smem transpose.
// cp.async double-buffered mainloop (2 K-chunks).
// ---------------------------------------------------------------------------
#define TP 68
#define SC_BUF (128 * LDP * 2)   // floats per buffer (A+B)

__global__ __launch_bounds__(256, 2) void scores_mma()
{
    int g = blockIdx.z;
    int bm = blockIdx.y * 128, bn = blockIdx.x * 128;
    const float* A = g_Q + (size_t)bm * FEAT + g * DK;
    const float* B = g_K + (size_t)bn * FEAT + g * DK;
    float* C  = g_E  + (size_t)g * MN;
    float* Ct = g_Et + (size_t)g * MN;

    extern __shared__ float dsm[];
    uint32_t smb = (uint32_t)__cvta_generic_to_shared(dsm);
    float* T = dsm;   // transpose buffer reuses the same smem after mainloop

    int tid = threadIdx.x, wid = tid >> 5, lane = tid & 31;
    int g4 = lane >> 2, tig = lane & 3;
    int wm = (wid & 1) * 64, wn = (wid >> 1) * 32;

    float acc[4][4][4];
#pragma unroll
    for (int i = 0; i < 4; i++)
#pragma unroll
        for (int j = 0; j < 4; j++)
#pragma unroll
            for (int q = 0; q < 4; q++) acc[i][j][q] = 0.0f;

    issue_chunk<128>(A, FEAT, smb, tid);
    issue_chunk<128>(B, FEAT, smb + 128 * LDP * 4u, tid);
    CP_COMMIT();
    // prefetch chunk 1 into buffer 1
    issue_chunk<128>(A + 32, FEAT, smb + SC_BUF * 4u, tid);
    issue_chunk<128>(B + 32, FEAT, smb + SC_BUF * 4u + 128 * LDP * 4u, tid);
    CP_COMMIT();

    for (int ch = 0; ch < 2; ch++) {
        if (ch == 0) CP_WAIT1(); else CP_WAIT0();
        __syncthreads();
        const uint32_t* As = (const uint32_t*)(dsm + ch * SC_BUF);
        const uint32_t* Bs = As + 128 * LDP;
#pragma unroll
        for (int kk = 0; kk < 4; kk++) {
            int k0 = kk * 8 + tig;
            uint32_t bf[4][2];
#pragma unroll
            for (int j = 0; j < 4; j++) {
                int rn = (wn + j * 8 + g4) * LDP;
                bf[j][0] = Bs[rn + k0];
                bf[j][1] = Bs[rn + k0 + 4];
            }
#pragma unroll
            for (int i = 0; i < 4; i++) {
                int r0 = (wm + i * 16 + g4) * LDP;
                uint32_t af[4];
                af[0] = As[r0 + k0];
                af[1] = As[r0 + 8 * LDP + k0];
                af[2] = As[r0 + k0 + 4];
                af[3] = As[r0 + 8 * LDP + k0 + 4];
#pragma unroll
                for (int j = 0; j < 4; j++) mma8(acc[i][j], af, bf[j]);
            }
        }
        __syncthreads();
    }

#pragma unroll
    for (int i = 0; i < 4; i++)
#pragma unroll
        for (int j = 0; j < 4; j++)
#pragma unroll
            for (int q = 0; q < 4; q++)
                acc[i][j][q] = __expf(acc[i][j][q] * 0.125f);

#pragma unroll
    for (int i = 0; i < 4; i++) {
        int row = bm + wm + i * 16 + g4;
#pragma unroll
        for (int j = 0; j < 4; j++) {
            int col = bn + wn + j * 8 + 2 * tig;
            float2 o0, o1;
            o0.x = acc[i][j][0]; o0.y = acc[i][j][1];
            o1.x = acc[i][j][2]; o1.y = acc[i][j][3];
            *(float2*)(C + (size_t)row * N_CTX + col)       = o0;
            *(float2*)(C + (size_t)(row + 8) * N_CTX + col) = o1;
        }
    }

    for (int hh = 0; hh < 2; hh++) {
        __syncthreads();
        if ((wid & 1) == hh) {
#pragma unroll
            for (int i = 0; i < 4; i++) {
                int rl = i * 16 + g4;
#pragma unroll
                for (int j = 0; j < 4; j++) {
                    int col = wn + j * 8 + 2 * tig;
                    T[col * TP + rl]            = acc[i][j][0];
                    T[(col + 1) * TP + rl]      = acc[i][j][1];
                    T[col * TP + rl + 8]        = acc[i][j][2];
                    T[(col + 1) * TP + rl + 8]  = acc[i][j][3];
                }
            }
        }
        __syncthreads();
        int col = tid >> 1, seg = (tid & 1) << 5;
        const float* src = T + col * TP + seg;
        float* dst = Ct + (size_t)(bn + col) * M_GT + bm + hh * 64 + seg;
#pragma unroll
        for (int k = 0; k < 8; k++)
            *(float4*)(dst + k * 4) = *(const float4*)(src + k * 4);
    }
}

// ---------------------------------------------------------------------------
// attn_mma: z 0..15 gt, z 16..31 ctx. 128x64 tiles, warp tile 64x16.
// Deferred softmax normalization: epilogue scales by 1/rowsum.
// ---------------------------------------------------------------------------
#define ATTN_BUF (128 * LDP + 64 * LDP)

__global__ __launch_bounds__(256, 2) void attn_mma(
    const float* __restrict__ b_conv, float* __restrict__ out_gt,
    float* __restrict__ out_ctx)
{
    int z = blockIdx.z;
    int g = z & 15;
    bool gt = z < 16;
    const float* A = gt ? g_L1 + (size_t)g * MN : g_L2 + (size_t)g * MN;
    const float* B = gt ? g_Vt + (size_t)(g * DK) * N_CTX
                        : g_Ut + (size_t)(g * DK) * M_GT;
    const float* RS = gt ? g_RS1 : g_RS2;
    float* C  = gt ? out_gt : out_ctx;
    int Mrows = gt ? M_GT : N_CTX;
    int Ktot  = gt ? N_CTX : M_GT;
    int bm = blockIdx.y * 128;
    if (bm >= Mrows) return;

    extern __shared__ float dsm[];
    uint32_t smb = (uint32_t)__cvta_generic_to_shared(dsm);
    __shared__ float rs_s[128];

    int tid = threadIdx.x, wid = tid >> 5, lane = tid & 31;
    int g4 = lane >> 2, tig = lane & 3;
    int wm = (wid & 1) * 64, wn = (wid >> 1) * 16;

    if (tid < 128) rs_s[tid] = RS[(size_t)g * Mrows + bm + tid];

    float acc[4][2][4];
#pragma unroll
    for (int i = 0; i < 4; i++)
#pragma unroll
        for (int j = 0; j < 2; j++)
#pragma unroll
            for (int q = 0; q < 4; q++) acc[i][j][q] = 0.0f;

    const float* Ab = A + (size_t)bm * Ktot;

    issue_chunk<128>(Ab, Ktot, smb, tid);
    issue_chunk<64>(B, Ktot, smb + 128 * LDP * 4u, tid);
    CP_COMMIT();

    int NCH = Ktot / 32;
    for (int ch = 0; ch < NCH; ch++) {
        int buf = ch & 1;
        if (ch + 1 < NCH) {
            uint32_t nb = smb + (uint32_t)((ch + 1) & 1) * ATTN_BUF * 4u;
            issue_chunk<128>(Ab + (ch + 1) * 32, Ktot, nb, tid);
            issue_chunk<64>(B + (ch + 1) * 32, Ktot, nb + 128 * LDP * 4u, tid);
            CP_COMMIT();
            CP_WAIT1();
        } else {
            CP_WAIT0();
        }
        __syncthreads();
        const uint32_t* As = (const uint32_t*)(dsm + buf * ATTN_BUF);
        const uint32_t* Bs = As + 128 * LDP;
#pragma unroll
        for (int kk = 0; kk < 4; kk++) {
            int k0 = kk * 8 + tig;
            uint32_t bf[2][2];
#pragma unroll
            for (int j = 0; j < 2; j++) {
                int rn = (wn + j * 8 + g4) * LDP;
                bf[j][0] = Bs[rn + k0];
                bf[j][1] = Bs[rn + k0 + 4];
            }
#pragma unroll
            for (int i = 0; i < 4; i++) {
                int r0 = (wm + i * 16 + g4) * LDP;
                uint32_t af[4];
                af[0] = As[r0 + k0];
                af[1] = As[r0 + 8 * LDP + k0];
                af[2] = As[r0 + k0 + 4];
                af[3] = As[r0 + 8 * LDP + k0 + 4];
#pragma unroll
                for (int j = 0; j < 2; j++) mma8(acc[i][j], af, bf[j]);
            }
        }
        __syncthreads();
    }

#pragma unroll
    for (int i = 0; i < 4; i++) {
        int rl = wm + i * 16 + g4;
        int row = bm + rl;
        float rinv0 = __frcp_rn(rs_s[rl]);
        float rinv1 = __frcp_rn(rs_s[rl + 8]);
#pragma unroll
        for (int j = 0; j < 2; j++) {
            int col = g * DK + wn + j * 8 + 2 * tig;
            float b0 = b_conv[col], b1 = b_conv[col + 1];
            float2 o0, o1;
            o0.x = acc[i][j][0] * rinv0 + b0; o0.y = acc[i][j][1] * rinv0 + b1;
            o1.x = acc[i][j][2] * rinv1 + b0; o1.y = acc[i][j][3] * rinv1 + b1;
            *(float2*)(C + (size_t)row * FEAT + col)       = o0;
            *(float2*)(C + (size_t)(row + 8) * FEAT + col) = o1;
        }
    }
}

// ---------------------------------------------------------------------------
// pos_soft<NCOLS>: fused pos-embedding + exp-weight product. Writes
// UNNORMALIZED weights w~ = tf32(max(pos+b,1e-6)*E) and rowsums RS[g][r].
// ---------------------------------------------------------------------------
template <int NCOLS>
__global__ __launch_bounds__(NCOLS / 4, 512 / (NCOLS / 4)) void pos_soft(
    const float4* __restrict__ boxA, const float4* __restrict__ boxB,
    const float* __restrict__ tabA, const float* __restrict__ tabB,
    const float* __restrict__ w_pos, const float* __restrict__ b_pos,
    const float* __restrict__ Eb, float* __restrict__ L, float* __restrict__ RS)
{
    constexpr int NT = NCOLS / 4;
    constexpr int NW = NT / 32;
    constexpr int SLP = NCOLS + 4;            // smem pitch
    extern __shared__ float sl[];             // [NG][SLP]
    __shared__ float wbh[16 * 68];            // w_pos tf32-hi, pitch 68
    __shared__ float wbl[16 * 68];            // w_pos tf32-lo
    __shared__ float bp[NG];
    __shared__ float rbuf[NG * NW];

    int tid = threadIdx.x, wid = tid >> 5, lane = tid & 31;
    int g4 = lane >> 2, tig = lane & 3;

    for (int i = tid; i < 1024; i += NT) {
        int g = i >> 6, f = i & 63;
        float w = w_pos[i];
        uint32_t hb = f2tf(w);
        float hf = __uint_as_float(hb);
        wbh[g * 68 + f] = hf;
        wbl[g * 68 + f] = __uint_as_float(f2tf(w - hf));
    }
    if (tid < NG) bp[tid] = b_pos[tid];
    __syncthreads();

    int r = blockIdx.x;
    float4 A = boxA[r];
    float bw = A.z - A.x + 1.0f, bh = A.w - A.y + 1.0f;
    float cx = 0.5f * (A.x + A.z), cy = 0.5f * (A.y + A.w);
    float rbw = 1.0f / bw, rbh = 1.0f / bh;
    float ivA = c_invdim[tig], ivB = c_invdim[tig + 4];

    const float* tr = tabA + (size_t)r * 36;
    float2 rw0 = *(const float2*)(tr + 2 * tig);
    float2 rw1 = *(const float2*)(tr + 2 * tig + 8);
    float2 rh0 = *(const float2*)(tr + 16 + 2 * tig);
    float2 rh1 = *(const float2*)(tr + 24 + 2 * tig);

    for (int mt = 0; mt < 8; mt++) {
        int base = wid * 128 + mt * 16;
        float a[2][8][2];   // [col ci][kk][k-half]
#pragma unroll
        for (int ci = 0; ci < 2; ci++) {
            int col = base + ci * 8 + g4;
            float4 Bx = boxB[col];
            float p0 = 100.0f * __logf(fmaxf(fabsf((cx - 0.5f * (Bx.x + Bx.z)) * rbw), 1e-3f));
            float p1 = 100.0f * __logf(fmaxf(fabsf((cy - 0.5f * (Bx.y + Bx.w)) * rbh), 1e-3f));
            float s, c;
            __sincosf(p0 * ivA, &s, &c);
            a[ci][0][0] = fmaxf(s, 0.0f); a[ci][1][0] = fmaxf(c, 0.0f);
            __sincosf(p0 * ivB, &s, &c);
            a[ci][0][1] = fmaxf(s, 0.0f); a[ci][1][1] = fmaxf(c, 0.0f);
            __sincosf(p1 * ivA, &s, &c);
            a[ci][2][0] = fmaxf(s, 0.0f); a[ci][3][0] = fmaxf(c, 0.0f);
            __sincosf(p1 * ivB, &s, &c);
            a[ci][2][1] = fmaxf(s, 0.0f); a[ci][3][1] = fmaxf(c, 0.0f);
            const float* tc = tabB + (size_t)col * 36;
            float2 cw0 = *(const float2*)(tc + 2 * tig);
            float2 cw1 = *(const float2*)(tc + 2 * tig + 8);
            float2 ch0 = *(const float2*)(tc + 16 + 2 * tig);
            float2 ch1 = *(const float2*)(tc + 24 + 2 * tig);
            a[ci][4][0] = fmaxf(cw0.x * rw0.y - cw0.y * rw0.x, 0.0f);
            a[ci][4][1] = fmaxf(cw1.x * rw1.y - cw1.y * rw1.x, 0.0f);
            a[ci][5][0] = fmaxf(cw0.y * rw0.y + cw0.x * rw0.x, 0.0f);
            a[ci][5][1] = fmaxf(cw1.y * rw1.y + cw1.x * rw1.x, 0.0f);
            a[ci][6][0] = fmaxf(ch0.x * rh0.y - ch0.y * rh0.x, 0.0f);
            a[ci][6][1] = fmaxf(ch1.x * rh1.y - ch1.y * rh1.x, 0.0f);
            a[ci][7][0] = fmaxf(ch0.y * rh0.y + ch0.x * rh0.x, 0.0f);
            a[ci][7][1] = fmaxf(ch1.y * rh1.y + ch1.x * rh1.x, 0.0f);
        }

        float acc[2][4];
#pragma unroll
        for (int j = 0; j < 2; j++)
#pragma unroll
            for (int q = 0; q < 4; q++) acc[j][q] = 0.0f;

#pragma unroll
        for (int kk = 0; kk < 8; kk++) {
            uint32_t ah[4], al[4];
#pragma unroll
            for (int q = 0; q < 4; q++) {
                float v = a[q & 1][kk][q >> 1];
                uint32_t h = f2tf(v);
                ah[q] = h;
                al[q] = f2tf(v - __uint_as_float(h));
            }
            int ko = 8 * kk + tig;
#pragma unroll
            for (int j = 0; j < 2; j++) {
                int rb = (8 * j + g4) * 68 + ko;
                uint32_t bh2[2], bl2[2];
                bh2[0] = __float_as_uint(wbh[rb]);
                bh2[1] = __float_as_uint(wbh[rb + 4]);
                bl2[0] = __float_as_uint(wbl[rb]);
                bl2[1] = __float_as_uint(wbl[rb + 4]);
                mma8(acc[j], ah, bh2);
                mma8(acc[j], ah, bl2);
                mma8(acc[j], al, bh2);
            }
        }

        int cA = base + g4, cB = cA + 8;
#pragma unroll
        for (int j = 0; j < 2; j++) {
            int ga = 8 * j + 2 * tig, gb = ga + 1;
            sl[ga * SLP + cA] = fmaxf(acc[j][0] + bp[ga], 1e-6f);
            sl[gb * SLP + cA] = fmaxf(acc[j][1] + bp[gb], 1e-6f);
            sl[ga * SLP + cB] = fmaxf(acc[j][2] + bp[ga], 1e-6f);
            sl[gb * SLP + cB] = fmaxf(acc[j][3] + bp[gb], 1e-6f);
        }
    }
    __syncthreads();

    // ---- phase 2: single pass: w~ = tf32(pos * E) -> L, accumulate rowsum --
    int c0 = tid * 4;
    size_t sro = (size_t)r * NCOLS + c0;
    float sum[NG];
#pragma unroll
    for (int g = 0; g < NG; g++) {
        float4 v = *(float4*)&sl[g * SLP + c0];
        float4 e = *(const float4*)(Eb + (size_t)g * MN + sro);
        v.x = f2tff(v.x * e.x); v.y = f2tff(v.y * e.y);
        v.z = f2tff(v.z * e.z); v.w = f2tff(v.w * e.w);
        *(float4*)(L + (size_t)g * MN + sro) = v;
        sum[g] = (v.x + v.y) + (v.z + v.w);
    }
#pragma unroll
    for (int g = 0; g < NG; g++) {
#pragma unroll
        for (int o = 16; o; o >>= 1)
            sum[g] += __shfl_xor_sync(0xffffffffu, sum[g], o);
    }
    if (lane == 0) {
#pragma unroll
        for (int g = 0; g < NG; g++) rbuf[g * NW + wid] = sum[g];
    }
    __syncthreads();
    if (tid < NG) {
        float t = 0.0f;
#pragma unroll
        for (int w = 0; w < NW; w++) t += rbuf[tid * NW + w];
        RS[(size_t)tid * gridDim.x + r] = t;
    }
}

// ---------------------------------------------------------------------------
extern "C" void kernel_launch(void* const* d_in, const int* in_sizes, int n_in,
                              void* d_out, int out_size)
{
    (void)in_sizes; (void)n_in; (void)out_size;
    const float* feat      = (const float*)d_in[0];
    const float* ctx_feat  = (const float*)d_in[1];
    const float* box       = (const float*)d_in[2];
    const float* ctx_box   = (const float*)d_in[3];
    const float* w_fc_gt   = (const float*)d_in[4];
    const float* b_fc_gt   = (const float*)d_in[5];
    const float* w_fc_ctx  = (const float*)d_in[6];
    const float* b_fc_ctx  = (const float*)d_in[7];
    const float* w_pos_gt  = (const float*)d_in[8];
    const float* b_pos_gt  = (const float*)d_in[9];
    const float* w_pos_ctx = (const float*)d_in[10];
    const float* b_pos_ctx = (const float*)d_in[11];
    const float* w_conv    = (const float*)d_in[12];
    const float* b_conv    = (const float*)d_in[13];

    float* out = (float*)d_out;
    float* out_gt  = out;
    float* out_ctx = out + (size_t)M_GT * FEAT;

    float *E, *Et, *L1, *L2, *RS1, *RS2, *tabA, *tabB;
    cudaGetSymbolAddress((void**)&E,    g_E);
    cudaGetSymbolAddress((void**)&Et,   g_Et);
    cudaGetSymbolAddress((void**)&L1,   g_L1);
    cudaGetSymbolAddress((void**)&L2,   g_L2);
    cudaGetSymbolAddress((void**)&RS1,  g_RS1);
    cudaGetSymbolAddress((void**)&RS2,  g_RS2);
    cudaGetSymbolAddress((void**)&tabA, g_tabA);
    cudaGetSymbolAddress((void**)&tabB, g_tabB);

    static int attr_done = 0;
    if (!attr_done) {
        cudaFuncSetAttribute(proj_mma, cudaFuncAttributeMaxDynamicSharedMemorySize,
                             2 * PROJ_BUF * 4);
        cudaFuncSetAttribute(scores_mma, cudaFuncAttributeMaxDynamicSharedMemorySize,
                             2 * SC_BUF * 4);
        cudaFuncSetAttribute(attn_mma, cudaFuncAttributeMaxDynamicSharedMemorySize,
                             2 * ATTN_BUF * 4);
        cudaFuncSetAttribute(pos_soft<N_CTX>, cudaFuncAttributeMaxDynamicSharedMemorySize,
                             NG * (N_CTX + 4) * 4);
        cudaFuncSetAttribute(pos_soft<M_GT>, cudaFuncAttributeMaxDynamicSharedMemorySize,
                             NG * (M_GT + 4) * 4);
        attr_done = 1;
    }

    // 1) Q, K, Ut, Vt projections + box tables (z=4 slice)
    proj_mma<<<dim3(8, 8, 5), 256, 2 * PROJ_BUF * 4>>>(
        feat, ctx_feat, w_fc_gt, b_fc_gt, w_fc_ctx, b_fc_ctx, w_conv,
        (const float4*)box, (const float4*)ctx_box);
    // 2) E = exp(scores), E + Et (cp.async pipelined)
    scores_mma<<<dim3(8, 4, 16), 256, 2 * SC_BUF * 4>>>();
    // 3) fused pos-embedding + exp-weight (unnormalized) + rowsums
    pos_soft<N_CTX><<<M_GT, N_CTX / 4, NG * (N_CTX + 4) * 4>>>(
        (const float4*)box, (const float4*)ctx_box, tabA, tabB,
        w_pos_gt, b_pos_gt, E, L1, RS1);
    pos_soft<M_GT><<<N_CTX, M_GT / 4, NG * (M_GT + 4) * 4>>>(
        (const float4*)ctx_box, (const float4*)box, tabB, tabA,
        w_pos_ctx, b_pos_ctx, Et, L2, RS2);
    // 4) attention output (deferred normalization in epilogue)
    attn_mma<<<dim3(1, 8, 32), 256, 2 * ATTN_BUF * 4>>>(b_conv, out_gt, out_ctx);
}